// round 2
// baseline (speedup 1.0000x reference)
#include <cuda_runtime.h>
#include <math.h>

#define Bsz 1024
#define Nn  63
#define Rr  (Bsz*Nn)      // 64512
#define HID 128
#define G3  384
#define XK  512
#define BMV 1000

// ---------------- scratch (static device allocations) ----------------
__device__ float g_x [(size_t)Rr*XK];        // [r][512] concat(opemb,c1,c2,bm)
__device__ float g_gi[(size_t)Nn*Bsz*G3];    // [n][b][384]
__device__ float g_H [(size_t)Nn*Bsz*HID];   // [n][b][128]
__device__ float g_WopT [96*128];            // [k][h]
__device__ float g_WpredT[64*128];
__device__ float g_WbmT [BMV*128];
__device__ float g_WihT [XK*G3];
__device__ float g_WhhT [HID*G3];
__device__ int   g_depth[Nn];

// ---------------- prep: transpose all weights to K-major ----------------
__global__ void k_prep(const float* __restrict__ Wop, const float* __restrict__ Wpred,
                       const float* __restrict__ Wbm, const float* __restrict__ Wih,
                       const float* __restrict__ Whh) {
    int i = blockIdx.x * blockDim.x + threadIdx.x;
    if (i < 128*96)   { int r=i/96,   c=i-r*96;   g_WopT [c*128+r] = Wop[i];  return; }
    i -= 128*96;
    if (i < 128*64)   { int r=i/64,   c=i-r*64;   g_WpredT[c*128+r]= Wpred[i];return; }
    i -= 128*64;
    if (i < 128*BMV)  { int r=i/BMV,  c=i-r*BMV;  g_WbmT [c*128+r] = Wbm[i];  return; }
    i -= 128*BMV;
    if (i < G3*XK)    { int r=i/XK,   c=i-r*XK;   g_WihT [c*G3+r]  = Wih[i];  return; }
    i -= G3*XK;
    if (i < G3*HID)   { int r=i/HID,  c=i-r*HID;  g_WhhT [c*G3+r]  = Whh[i];  return; }
}

__global__ void k_depth(const int* __restrict__ li) {
    if (threadIdx.x == 0 && blockIdx.x == 0) {
        for (int i = 0; i < Nn; i++) {
            int l = li[i];
            g_depth[i] = (l < 0) ? 1 : (g_depth[l] + 1);  // postorder: child before parent
        }
    }
}

// ---------------- opemb: x[:,0:128] = concat(op,extra) @ WopT + b_op ----------------
__global__ __launch_bounds__(256) void k_opemb(const float* __restrict__ op,
                                               const float* __restrict__ ex,
                                               const float* __restrict__ bop) {
    __shared__ float As[16][68];
    __shared__ float Bs[16][128];
    const int t = threadIdx.x;
    const int rbase = blockIdx.x * 64;
    const int ty = t >> 5, tx = t & 31;
    const int row0 = ty * 8, col0 = tx * 4;
    float acc[8][4];
#pragma unroll
    for (int i = 0; i < 8; i++)
#pragma unroll
        for (int j = 0; j < 4; j++) acc[i][j] = 0.f;

    for (int kt = 0; kt < 96; kt += 16) {
#pragma unroll
        for (int i = 0; i < 4; i++) {
            int idx = t + i * 256;
            int row = idx >> 4, kk = idx & 15;
            int k = kt + kk;
            As[kk][row] = (k < 32) ? op[(size_t)(rbase+row)*32 + k]
                                   : ex[(size_t)(rbase+row)*64 + (k-32)];
        }
#pragma unroll
        for (int i = 0; i < 8; i++) {
            int idx = t + i * 256;
            int kk = idx >> 7, c = idx & 127;
            Bs[kk][c] = g_WopT[(kt+kk)*128 + c];
        }
        __syncthreads();
#pragma unroll
        for (int kk = 0; kk < 16; kk++) {
            float4 a0 = *(const float4*)&As[kk][row0];
            float4 a1 = *(const float4*)&As[kk][row0+4];
            float4 b  = *(const float4*)&Bs[kk][col0];
            float a[8] = {a0.x,a0.y,a0.z,a0.w,a1.x,a1.y,a1.z,a1.w};
            float bb[4]= {b.x,b.y,b.z,b.w};
#pragma unroll
            for (int i = 0; i < 8; i++)
#pragma unroll
                for (int j = 0; j < 4; j++) acc[i][j] += a[i]*bb[j];
        }
        __syncthreads();
    }
#pragma unroll
    for (int i = 0; i < 8; i++) {
        int r = rbase + row0 + i;
#pragma unroll
        for (int j = 0; j < 4; j++)
            g_x[(size_t)r*XK + col0 + j] = acc[i][j] + bop[col0+j];
    }
}

// ---------------- preds: x[:,128:256]=c1, x[:,256:384]=c2 (min over P=8) ----------------
__global__ __launch_bounds__(256) void k_pred(const float* __restrict__ p1,
                                              const float* __restrict__ p2,
                                              const int* __restrict__ c1p,
                                              const int* __restrict__ c2p,
                                              const float* __restrict__ bpred) {
    __shared__ float Wp[64*128];   // [k][h]
    __shared__ float Ps[32][65];   // [row][k]
    const float* preds = blockIdx.y ? p2 : p1;
    const int*   cond  = blockIdx.y ? c2p : c1p;
    const int xoff = blockIdx.y ? 256 : 128;
    const int t = threadIdx.x;
    const int rbase = blockIdx.x * 32;
#pragma unroll
    for (int i = 0; i < 32; i++) Wp[t + i*256] = g_WpredT[t + i*256];
    const int ty = t >> 5, tx = t & 31;
    const int row0 = ty * 4, col0 = tx * 4;
    float4 bp4 = *(const float4*)&bpred[col0];
    float bp[4] = {bp4.x,bp4.y,bp4.z,bp4.w};
    float macc[4][4];
#pragma unroll
    for (int i = 0; i < 4; i++)
#pragma unroll
        for (int j = 0; j < 4; j++) macc[i][j] = 1e30f;

    for (int p = 0; p < 8; p++) {
        __syncthreads();
#pragma unroll
        for (int i = 0; i < 8; i++) {
            int idx = t + i * 256;
            int row = idx >> 6, k = idx & 63;
            Ps[row][k] = preds[((size_t)(rbase+row)*8 + p)*64 + k];
        }
        __syncthreads();
        float acc[4][4];
#pragma unroll
        for (int i = 0; i < 4; i++)
#pragma unroll
            for (int j = 0; j < 4; j++) acc[i][j] = 0.f;
#pragma unroll 8
        for (int k = 0; k < 64; k++) {
            float4 w = *(const float4*)&Wp[k*128 + col0];
            float wv[4] = {w.x,w.y,w.z,w.w};
            float a[4];
#pragma unroll
            for (int i = 0; i < 4; i++) a[i] = Ps[row0+i][k];
#pragma unroll
            for (int i = 0; i < 4; i++)
#pragma unroll
                for (int j = 0; j < 4; j++) acc[i][j] += a[i]*wv[j];
        }
#pragma unroll
        for (int i = 0; i < 4; i++)
#pragma unroll
            for (int j = 0; j < 4; j++)
                macc[i][j] = fminf(macc[i][j], acc[i][j] + bp[j]);
    }
#pragma unroll
    for (int i = 0; i < 4; i++) {
        int r = rbase + row0 + i;
        float pres = (float)cond[r];
#pragma unroll
        for (int j = 0; j < 4; j++)
            g_x[(size_t)r*XK + xoff + col0 + j] = macc[i][j] * pres;
    }
}

// ---------------- bitmap: x[:,384:512] = (bitmap @ WbmT + b_bm) * has_cond ----------------
__global__ __launch_bounds__(256) void k_bm(const float* __restrict__ bm,
                                            const float* __restrict__ bbm,
                                            const int* __restrict__ hc) {
    __shared__ float As[20][68];
    __shared__ float Bs[20][128];
    const int t = threadIdx.x;
    const int rbase = blockIdx.x * 64;
    const int ty = t >> 5, tx = t & 31;
    const int row0 = ty * 8, col0 = tx * 4;
    float acc[8][4];
#pragma unroll
    for (int i = 0; i < 8; i++)
#pragma unroll
        for (int j = 0; j < 4; j++) acc[i][j] = 0.f;

    for (int kt = 0; kt < BMV; kt += 20) {
#pragma unroll
        for (int i = 0; i < 5; i++) {
            int idx = t + i * 256;         // 1280 = 64*20
            int row = idx / 20, kk = idx - row*20;
            As[kk][row] = bm[(size_t)(rbase+row)*BMV + kt + kk];
        }
#pragma unroll
        for (int i = 0; i < 10; i++) {
            int idx = t + i * 256;         // 2560 = 20*128
            int kk = idx >> 7, c = idx & 127;
            Bs[kk][c] = g_WbmT[(kt+kk)*128 + c];
        }
        __syncthreads();
#pragma unroll
        for (int kk = 0; kk < 20; kk++) {
            float4 a0 = *(const float4*)&As[kk][row0];
            float4 a1 = *(const float4*)&As[kk][row0+4];
            float4 b  = *(const float4*)&Bs[kk][col0];
            float a[8] = {a0.x,a0.y,a0.z,a0.w,a1.x,a1.y,a1.z,a1.w};
            float bb[4]= {b.x,b.y,b.z,b.w};
#pragma unroll
            for (int i = 0; i < 8; i++)
#pragma unroll
                for (int j = 0; j < 4; j++) acc[i][j] += a[i]*bb[j];
        }
        __syncthreads();
    }
#pragma unroll
    for (int i = 0; i < 8; i++) {
        int r = rbase + row0 + i;
        float has = (float)hc[r];
#pragma unroll
        for (int j = 0; j < 4; j++)
            g_x[(size_t)r*XK + 384 + col0 + j] = (acc[i][j] + bbm[col0+j]) * has;
    }
}

// ---------------- gi: [n][b][384] = x @ WihT + b_ih (with (b,n)->(n,b) swizzle) ----------------
__global__ __launch_bounds__(256) void k_gi(const float* __restrict__ bih) {
    __shared__ float As[16][68];
    __shared__ float Bs[16][128];
    const int t = threadIdx.x;
    const int rbase = blockIdx.x * 64;
    const int cbase = blockIdx.y * 128;
    const int ty = t >> 5, tx = t & 31;
    const int row0 = ty * 8, col0 = tx * 4;
    float acc[8][4];
#pragma unroll
    for (int i = 0; i < 8; i++)
#pragma unroll
        for (int j = 0; j < 4; j++) acc[i][j] = 0.f;

    for (int kt = 0; kt < XK; kt += 16) {
#pragma unroll
        for (int i = 0; i < 4; i++) {
            int idx = t + i * 256;
            int row = idx >> 4, kk = idx & 15;
            As[kk][row] = g_x[(size_t)(rbase+row)*XK + kt + kk];
        }
#pragma unroll
        for (int i = 0; i < 8; i++) {
            int idx = t + i * 256;
            int kk = idx >> 7, c = idx & 127;
            Bs[kk][c] = g_WihT[(kt+kk)*G3 + cbase + c];
        }
        __syncthreads();
#pragma unroll
        for (int kk = 0; kk < 16; kk++) {
            float4 a0 = *(const float4*)&As[kk][row0];
            float4 a1 = *(const float4*)&As[kk][row0+4];
            float4 b  = *(const float4*)&Bs[kk][col0];
            float a[8] = {a0.x,a0.y,a0.z,a0.w,a1.x,a1.y,a1.z,a1.w};
            float bb[4]= {b.x,b.y,b.z,b.w};
#pragma unroll
            for (int i = 0; i < 8; i++)
#pragma unroll
                for (int j = 0; j < 4; j++) acc[i][j] += a[i]*bb[j];
        }
        __syncthreads();
    }
#pragma unroll
    for (int i = 0; i < 8; i++) {
        int r = rbase + row0 + i;
        int n = r % Nn, b = r / Nn;
#pragma unroll
        for (int j = 0; j < 4; j++) {
            int g = cbase + col0 + j;
            g_gi[((size_t)n*Bsz + b)*G3 + g] = acc[i][j] + bih[g];
        }
    }
}

// ---------------- GRU level step: one launch per tree level ----------------
__global__ __launch_bounds__(512) void k_recur(const int* __restrict__ li,
                                               const int* __restrict__ ri,
                                               const float* __restrict__ bhh,
                                               int level) {
    const int node = blockIdx.y;
    if (g_depth[node] != level) return;
    const int b0 = blockIdx.x * 64;
    const int t  = threadIdx.x;
    const int l  = li[node], r = ri[node];

    if (l < 0) {  // leaf: h = 0, gh_ = b_hh
#pragma unroll
        for (int i = 0; i < 16; i++) {
            int idx = t + i * 512;
            int row = idx >> 7, g = idx & 127;
            int b = b0 + row;
            size_t gib = ((size_t)node*Bsz + b)*G3;
            float ir = g_gi[gib + g], iz = g_gi[gib + 128 + g], in_ = g_gi[gib + 256 + g];
            float rg = 1.f/(1.f + expf(-(ir + bhh[g])));
            float zg = 1.f/(1.f + expf(-(iz + bhh[128+g])));
            float ng = tanhf(in_ + rg * bhh[256+g]);
            g_H[((size_t)node*Bsz + b)*HID + g] = (1.f - zg) * ng;
        }
        return;
    }

    __shared__ float hs[16][68];
    __shared__ float Ws[16][G3];
    const int ty = t >> 5, tx = t & 31;
    const int row0 = ty * 4, col0 = tx * 4;
    float aR[4][4], aZ[4][4], aN[4][4];
#pragma unroll
    for (int i = 0; i < 4; i++)
#pragma unroll
        for (int j = 0; j < 4; j++) { aR[i][j]=0.f; aZ[i][j]=0.f; aN[i][j]=0.f; }

    const float* Hl = &g_H[(size_t)l*Bsz*HID];
    const float* Hr = &g_H[(size_t)r*Bsz*HID];

    for (int kt = 0; kt < HID; kt += 16) {
#pragma unroll
        for (int i = 0; i < 2; i++) {
            int idx = t + i * 512;
            int row = idx >> 4, kk = idx & 15;
            int ga = (b0+row)*HID + kt + kk;
            hs[kk][row] = 0.5f*(Hl[ga] + Hr[ga]);
        }
#pragma unroll
        for (int i = 0; i < 12; i++) {
            int idx = t + i * 512;         // 6144 = 16*384
            int kk = idx / G3, c = idx - kk*G3;
            Ws[kk][c] = g_WhhT[(kt+kk)*G3 + c];
        }
        __syncthreads();
#pragma unroll
        for (int kk = 0; kk < 16; kk++) {
            float4 a  = *(const float4*)&hs[kk][row0];
            float4 wr = *(const float4*)&Ws[kk][col0];
            float4 wz = *(const float4*)&Ws[kk][128 + col0];
            float4 wn = *(const float4*)&Ws[kk][256 + col0];
            float av[4] = {a.x,a.y,a.z,a.w};
            float vr[4] = {wr.x,wr.y,wr.z,wr.w};
            float vz[4] = {wz.x,wz.y,wz.z,wz.w};
            float vn[4] = {wn.x,wn.y,wn.z,wn.w};
#pragma unroll
            for (int i = 0; i < 4; i++)
#pragma unroll
                for (int j = 0; j < 4; j++) {
                    aR[i][j] += av[i]*vr[j];
                    aZ[i][j] += av[i]*vz[j];
                    aN[i][j] += av[i]*vn[j];
                }
        }
        __syncthreads();
    }

#pragma unroll
    for (int i = 0; i < 4; i++) {
        int b = b0 + row0 + i;
        size_t gib = ((size_t)node*Bsz + b)*G3;
        size_t hb  = ((size_t)node*Bsz + b)*HID;
        int ha = b * HID;
#pragma unroll
        for (int j = 0; j < 4; j++) {
            int g = col0 + j;
            float hv = 0.5f*(Hl[ha+g] + Hr[ha+g]);
            float rg = 1.f/(1.f + expf(-(g_gi[gib + g]       + aR[i][j] + bhh[g])));
            float zg = 1.f/(1.f + expf(-(g_gi[gib + 128 + g] + aZ[i][j] + bhh[128+g])));
            float ng = tanhf(g_gi[gib + 256 + g] + rg*(aN[i][j] + bhh[256+g]));
            g_H[hb + g] = (1.f - zg)*ng + zg*hv;
        }
    }
}

// ---------------- heads: two 128->128->128->1 MLPs on the root hidden ----------------
__global__ __launch_bounds__(128) void k_heads(const float* __restrict__ W2a, const float* __restrict__ b2a,
                                               const float* __restrict__ W3a, const float* __restrict__ b3a,
                                               const float* __restrict__ Woa, const float* __restrict__ boa,
                                               const float* __restrict__ W2b, const float* __restrict__ b2b,
                                               const float* __restrict__ W3b, const float* __restrict__ b3b,
                                               const float* __restrict__ Wob, const float* __restrict__ bob,
                                               float* __restrict__ out) {
    const int b = blockIdx.x, head = blockIdx.y, t = threadIdx.x;
    const float* W2 = head ? W2b : W2a;  const float* b2 = head ? b2b : b2a;
    const float* W3 = head ? W3b : W3a;  const float* b3 = head ? b3b : b3a;
    const float* Wo = head ? Wob : Woa;  const float* bo = head ? bob : boa;

    __shared__ float s0[128], s1[128], red[4];
    s0[t] = g_H[((size_t)(Nn-1)*Bsz + b)*HID + t];
    __syncthreads();
    float acc = b2[t];
#pragma unroll 8
    for (int k = 0; k < 128; k++) acc += s0[k] * W2[t*128 + k];
    s1[t] = fmaxf(acc, 0.f);
    __syncthreads();
    acc = b3[t];
#pragma unroll 8
    for (int k = 0; k < 128; k++) acc += s1[k] * W3[t*128 + k];
    float h2 = fmaxf(acc, 0.f);
    float v = h2 * Wo[t];
#pragma unroll
    for (int off = 16; off; off >>= 1) v += __shfl_down_sync(0xffffffffu, v, off);
    if ((t & 31) == 0) red[t >> 5] = v;
    __syncthreads();
    if (t == 0) {
        float s = red[0] + red[1] + red[2] + red[3] + bo[0];
        out[head * Bsz + b] = 1.f/(1.f + expf(-s));
    }
}

// ---------------- launcher ----------------
extern "C" void kernel_launch(void* const* d_in, const int* in_sizes, int n_in,
                              void* d_out, int out_size) {
    const float* op    = (const float*)d_in[0];
    const float* ex    = (const float*)d_in[1];
    const float* p1    = (const float*)d_in[2];
    const float* p2    = (const float*)d_in[3];
    const int*   c1p   = (const int*)  d_in[4];
    const int*   c2p   = (const int*)  d_in[5];
    const int*   hc    = (const int*)  d_in[6];
    const float* bmp   = (const float*)d_in[7];
    const int*   li    = (const int*)  d_in[8];
    const int*   ri    = (const int*)  d_in[9];
    const float* Wop   = (const float*)d_in[10];
    const float* bop   = (const float*)d_in[11];
    const float* Wpred = (const float*)d_in[12];
    const float* bpred = (const float*)d_in[13];
    const float* Wbm   = (const float*)d_in[14];
    const float* bbm   = (const float*)d_in[15];
    const float* Wih   = (const float*)d_in[16];
    const float* bih   = (const float*)d_in[17];
    const float* Whh   = (const float*)d_in[18];
    const float* bhh   = (const float*)d_in[19];
    const float* W2t1  = (const float*)d_in[20];
    const float* b2t1  = (const float*)d_in[21];
    const float* W3t1  = (const float*)d_in[22];
    const float* b3t1  = (const float*)d_in[23];
    const float* Wot1  = (const float*)d_in[24];
    const float* bot1  = (const float*)d_in[25];
    const float* W2t2  = (const float*)d_in[26];
    const float* b2t2  = (const float*)d_in[27];
    const float* W3t2  = (const float*)d_in[28];
    const float* b3t2  = (const float*)d_in[29];
    const float* Wot2  = (const float*)d_in[30];
    const float* bot2  = (const float*)d_in[31];
    float* out = (float*)d_out;

    k_prep<<<1540, 256>>>(Wop, Wpred, Wbm, Wih, Whh);
    k_depth<<<1, 1>>>(li);
    k_opemb<<<Rr/64, 256>>>(op, ex, bop);
    k_pred<<<dim3(Rr/32, 2), 256>>>(p1, p2, c1p, c2p, bpred);
    k_bm<<<Rr/64, 256>>>(bmp, bbm, hc);
    k_gi<<<dim3(Rr/64, 3), 256>>>(bih);
    for (int lvl = 1; lvl <= 6; lvl++)
        k_recur<<<dim3(Bsz/64, Nn), 512>>>(li, ri, bhh, lvl);
    k_heads<<<dim3(Bsz, 2), 128>>>(W2t1, b2t1, W3t1, b3t1, Wot1, bot1,
                                   W2t2, b2t2, W3t2, b3t2, Wot2, bot2, out);
}

// round 3
// speedup vs baseline: 1.7696x; 1.7696x over previous
#include <cuda_runtime.h>
#include <math.h>

#define Bsz 1024
#define Nn  63
#define Rr  (Bsz*Nn)      // 64512
#define HID 128
#define G3  384
#define XK  512
#define BMV 1000

// ---------------- scratch ----------------
__device__ float g_x [(size_t)Rr*XK];        // [r][512] concat(opemb,c1,c2,bm)
__device__ float g_gi[(size_t)Nn*Bsz*G3];    // [n][b][384]
__device__ float g_H [(size_t)Nn*Bsz*HID];   // [n][b][128]
__device__ float g_WopT [96*128];            // [k][h]
__device__ float g_WhhT [HID*G3];
__device__ int   g_depth[Nn];

// ---------------- prep: transpose small weights used by fp32 kernels ----------------
__global__ void k_prep(const float* __restrict__ Wop, const float* __restrict__ Whh) {
    int i = blockIdx.x * blockDim.x + threadIdx.x;
    if (i < 128*96)   { int r=i/96,   c=i-r*96;   g_WopT [c*128+r] = Wop[i];  return; }
    i -= 128*96;
    if (i < G3*HID)   { int r=i/HID,  c=i-r*HID;  g_WhhT [c*G3+r]  = Whh[i];  return; }
}

__global__ void k_depth(const int* __restrict__ li) {
    if (threadIdx.x == 0 && blockIdx.x == 0) {
        for (int i = 0; i < Nn; i++) {
            int l = li[i];
            g_depth[i] = (l < 0) ? 1 : (g_depth[l] + 1);
        }
    }
}

// ================= tf32 MMA machinery =================
__device__ __forceinline__ unsigned f2tf32(float f) {
    unsigned u;
    asm("cvt.rna.tf32.f32 %0, %1;" : "=r"(u) : "f"(f));
    return u;
}

__device__ __forceinline__ void mma_tf32(float c[4], unsigned a0, unsigned a1,
                                         unsigned a2, unsigned a3,
                                         unsigned b0, unsigned b1) {
    asm volatile("mma.sync.aligned.m16n8k8.row.col.f32.tf32.tf32.f32 "
                 "{%0,%1,%2,%3}, {%4,%5,%6,%7}, {%8,%9}, {%0,%1,%2,%3};"
                 : "+f"(c[0]), "+f"(c[1]), "+f"(c[2]), "+f"(c[3])
                 : "r"(a0), "r"(a1), "r"(a2), "r"(a3), "r"(b0), "r"(b1));
}

#define SMPAD 36

// stage 128 rows x up-to-32 k of src (row-major, stride ld) into smem as tf32
__device__ __forceinline__ void stage128(unsigned* S, const float* __restrict__ src,
                                         int ld, int rbase, int kt, int Ktot, int t) {
    int tr = t >> 3;
    int k4 = (t & 7) * 4;
    bool ok = (kt + k4 < Ktot);
#pragma unroll
    for (int p = 0; p < 4; p++) {
        int row = p * 32 + tr;
        float4 v = make_float4(0.f, 0.f, 0.f, 0.f);
        if (ok) v = *(const float4*)&src[(size_t)(rbase + row) * ld + kt + k4];
        unsigned* d = &S[row * SMPAD + k4];
        d[0] = f2tf32(v.x); d[1] = f2tf32(v.y); d[2] = f2tf32(v.z); d[3] = f2tf32(v.w);
    }
}

// one k8 step: 2 m-tiles x 8 n-tiles of mma into c[2][8][4]
__device__ __forceinline__ void mma_step(const unsigned* As, const unsigned* Bs,
                                         int k0, int wm, int wn, int lane,
                                         float c[2][8][4]) {
    const int qr = lane >> 2, qc = lane & 3;
    unsigned a[2][4];
#pragma unroll
    for (int mt = 0; mt < 2; mt++) {
        int m = wm * 32 + mt * 16 + qr;
        a[mt][0] = As[m * SMPAD + k0 + qc];
        a[mt][1] = As[(m + 8) * SMPAD + k0 + qc];
        a[mt][2] = As[m * SMPAD + k0 + qc + 4];
        a[mt][3] = As[(m + 8) * SMPAD + k0 + qc + 4];
    }
#pragma unroll
    for (int nt = 0; nt < 8; nt++) {
        int n = wn * 64 + nt * 8 + qr;
        unsigned b0 = Bs[n * SMPAD + k0 + qc];
        unsigned b1 = Bs[n * SMPAD + k0 + qc + 4];
#pragma unroll
        for (int mt = 0; mt < 2; mt++)
            mma_tf32(c[mt][nt], a[mt][0], a[mt][1], a[mt][2], a[mt][3], b0, b1);
    }
}

// full mainloop: C[128x128] = A[rbase:+128, :Ktot] @ B[cbase:+128, :Ktot]^T
__device__ __forceinline__ void mm128(const float* __restrict__ A, int lda,
                                      const float* __restrict__ B, int ldb,
                                      int Ktot, int rbase, int cbase,
                                      unsigned* As, unsigned* Bs,
                                      int t, int wm, int wn, int lane,
                                      float c[2][8][4]) {
#pragma unroll
    for (int mt = 0; mt < 2; mt++)
#pragma unroll
        for (int nt = 0; nt < 8; nt++)
#pragma unroll
            for (int j = 0; j < 4; j++) c[mt][nt][j] = 0.f;

    for (int kt = 0; kt < Ktot; kt += 32) {
        int kw = min(32, Ktot - kt);
        __syncthreads();
        stage128(As, A, lda, rbase, kt, Ktot, t);
        stage128(Bs, B, ldb, cbase, kt, Ktot, t);
        __syncthreads();
        int steps = kw >> 3;
        if (steps == 4) {
#pragma unroll
            for (int ks = 0; ks < 4; ks++) mma_step(As, Bs, ks * 8, wm, wn, lane, c);
        } else {
            for (int ks = 0; ks < steps; ks++) mma_step(As, Bs, ks * 8, wm, wn, lane, c);
        }
    }
}

// ---------------- pred (tf32): min over P=8, per cond ----------------
__global__ __launch_bounds__(256) void k_pred_mma(const float* __restrict__ p1,
                                                  const float* __restrict__ p2,
                                                  const int* __restrict__ c1p,
                                                  const int* __restrict__ c2p,
                                                  const float* __restrict__ Wpred,
                                                  const float* __restrict__ bpred) {
    __shared__ unsigned As[128 * SMPAD];
    __shared__ unsigned Bs[128 * SMPAD];
    const float* preds = blockIdx.y ? p2 : p1;
    const int*   cond  = blockIdx.y ? c2p : c1p;
    const int xoff = blockIdx.y ? 256 : 128;
    const int t = threadIdx.x, lane = t & 31, warp = t >> 5;
    const int wm = warp >> 1, wn = warp & 1;
    const int rbase = blockIdx.x * 128;          // p-rows (516096 total)
    float c[2][8][4];
    mm128(preds, 64, Wpred, 64, 64, rbase, 0, As, Bs, t, wm, wn, lane, c);

    const int qc = lane & 3;
#pragma unroll
    for (int mt = 0; mt < 2; mt++) {
#pragma unroll
        for (int nt = 0; nt < 8; nt++) {
#pragma unroll
            for (int j = 0; j < 4; j++) {
                float v = c[mt][nt][j];
                v = fminf(v, __shfl_xor_sync(0xffffffffu, v, 4));
                v = fminf(v, __shfl_xor_sync(0xffffffffu, v, 8));
                v = fminf(v, __shfl_xor_sync(0xffffffffu, v, 16));
                c[mt][nt][j] = v;
            }
        }
    }
    if (lane < 4) {
#pragma unroll
        for (int mt = 0; mt < 2; mt++) {
            int or0 = (rbase + wm * 32 + mt * 16) >> 3;   // output row for regs 0,1
#pragma unroll
            for (int nt = 0; nt < 8; nt++) {
#pragma unroll
                for (int j = 0; j < 4; j++) {
                    int orow = or0 + ((j >= 2) ? 1 : 0);
                    int col = wn * 64 + nt * 8 + qc * 2 + (j & 1);
                    float val = (c[mt][nt][j] + bpred[col]) * (float)cond[orow];
                    g_x[(size_t)orow * XK + xoff + col] = val;
                }
            }
        }
    }
}

// ---------------- bitmap (tf32) ----------------
__global__ __launch_bounds__(256) void k_bm_mma(const float* __restrict__ bm,
                                                const float* __restrict__ Wbm,
                                                const float* __restrict__ bbm,
                                                const int* __restrict__ hc) {
    __shared__ unsigned As[128 * SMPAD];
    __shared__ unsigned Bs[128 * SMPAD];
    const int t = threadIdx.x, lane = t & 31, warp = t >> 5;
    const int wm = warp >> 1, wn = warp & 1;
    const int rbase = blockIdx.x * 128;
    float c[2][8][4];
    mm128(bm, BMV, Wbm, BMV, BMV, rbase, 0, As, Bs, t, wm, wn, lane, c);

    const int qr = lane >> 2, qc = lane & 3;
#pragma unroll
    for (int mt = 0; mt < 2; mt++) {
#pragma unroll
        for (int j = 0; j < 4; j++) {
            int r = rbase + wm * 32 + mt * 16 + qr + ((j >= 2) ? 8 : 0);
            float has = (float)hc[r];
#pragma unroll
            for (int nt = 0; nt < 8; nt++) {
                int col = wn * 64 + nt * 8 + qc * 2 + (j & 1);
                g_x[(size_t)r * XK + 384 + col] = (c[mt][nt][j] + bbm[col]) * has;
            }
        }
    }
}

// ---------------- gi (tf32): g_gi[n][b][g] = x @ Wih^T + b_ih ----------------
__global__ __launch_bounds__(256) void k_gi_mma(const float* __restrict__ Wih,
                                                const float* __restrict__ bih) {
    __shared__ unsigned As[128 * SMPAD];
    __shared__ unsigned Bs[128 * SMPAD];
    const int t = threadIdx.x, lane = t & 31, warp = t >> 5;
    const int wm = warp >> 1, wn = warp & 1;
    const int rbase = blockIdx.x * 128;
    const int cbase = blockIdx.y * 128;
    float c[2][8][4];
    mm128(g_x, XK, Wih, XK, XK, rbase, cbase, As, Bs, t, wm, wn, lane, c);

    const int qr = lane >> 2, qc = lane & 3;
#pragma unroll
    for (int mt = 0; mt < 2; mt++) {
#pragma unroll
        for (int j = 0; j < 4; j++) {
            int r = rbase + wm * 32 + mt * 16 + qr + ((j >= 2) ? 8 : 0);
            int n = r % Nn, b = r / Nn;
            size_t obase = ((size_t)n * Bsz + b) * G3;
#pragma unroll
            for (int nt = 0; nt < 8; nt++) {
                int g = cbase + wn * 64 + nt * 8 + qc * 2 + (j & 1);
                g_gi[obase + g] = c[mt][nt][j] + bih[g];
            }
        }
    }
}

// ---------------- opemb (fp32, small) ----------------
__global__ __launch_bounds__(256) void k_opemb(const float* __restrict__ op,
                                               const float* __restrict__ ex,
                                               const float* __restrict__ bop) {
    __shared__ float As[16][68];
    __shared__ float Bs[16][128];
    const int t = threadIdx.x;
    const int rbase = blockIdx.x * 64;
    const int ty = t >> 5, tx = t & 31;
    const int row0 = ty * 8, col0 = tx * 4;
    float acc[8][4];
#pragma unroll
    for (int i = 0; i < 8; i++)
#pragma unroll
        for (int j = 0; j < 4; j++) acc[i][j] = 0.f;

    for (int kt = 0; kt < 96; kt += 16) {
#pragma unroll
        for (int i = 0; i < 4; i++) {
            int idx = t + i * 256;
            int row = idx >> 4, kk = idx & 15;
            int k = kt + kk;
            As[kk][row] = (k < 32) ? op[(size_t)(rbase+row)*32 + k]
                                   : ex[(size_t)(rbase+row)*64 + (k-32)];
        }
#pragma unroll
        for (int i = 0; i < 8; i++) {
            int idx = t + i * 256;
            int kk = idx >> 7, c = idx & 127;
            Bs[kk][c] = g_WopT[(kt+kk)*128 + c];
        }
        __syncthreads();
#pragma unroll
        for (int kk = 0; kk < 16; kk++) {
            float4 a0 = *(const float4*)&As[kk][row0];
            float4 a1 = *(const float4*)&As[kk][row0+4];
            float4 b  = *(const float4*)&Bs[kk][col0];
            float a[8] = {a0.x,a0.y,a0.z,a0.w,a1.x,a1.y,a1.z,a1.w};
            float bb[4]= {b.x,b.y,b.z,b.w};
#pragma unroll
            for (int i = 0; i < 8; i++)
#pragma unroll
                for (int j = 0; j < 4; j++) acc[i][j] += a[i]*bb[j];
        }
        __syncthreads();
    }
#pragma unroll
    for (int i = 0; i < 8; i++) {
        int r = rbase + row0 + i;
#pragma unroll
        for (int j = 0; j < 4; j++)
            g_x[(size_t)r*XK + col0 + j] = acc[i][j] + bop[col0+j];
    }
}

// ---------------- GRU level step (fp32) ----------------
__global__ __launch_bounds__(512) void k_recur(const int* __restrict__ li,
                                               const int* __restrict__ ri,
                                               const float* __restrict__ bhh,
                                               int level) {
    const int node = blockIdx.y;
    if (g_depth[node] != level) return;
    const int b0 = blockIdx.x * 64;
    const int t  = threadIdx.x;
    const int l  = li[node], r = ri[node];

    if (l < 0) {  // leaf
#pragma unroll
        for (int i = 0; i < 16; i++) {
            int idx = t + i * 512;
            int row = idx >> 7, g = idx & 127;
            int b = b0 + row;
            size_t gib = ((size_t)node*Bsz + b)*G3;
            float ir = g_gi[gib + g], iz = g_gi[gib + 128 + g], in_ = g_gi[gib + 256 + g];
            float rg = 1.f/(1.f + expf(-(ir + bhh[g])));
            float zg = 1.f/(1.f + expf(-(iz + bhh[128+g])));
            float ng = tanhf(in_ + rg * bhh[256+g]);
            g_H[((size_t)node*Bsz + b)*HID + g] = (1.f - zg) * ng;
        }
        return;
    }

    __shared__ float hs[16][68];
    __shared__ float Ws[16][G3];
    const int ty = t >> 5, tx = t & 31;
    const int row0 = ty * 4, col0 = tx * 4;
    float aR[4][4], aZ[4][4], aN[4][4];
#pragma unroll
    for (int i = 0; i < 4; i++)
#pragma unroll
        for (int j = 0; j < 4; j++) { aR[i][j]=0.f; aZ[i][j]=0.f; aN[i][j]=0.f; }

    const float* Hl = &g_H[(size_t)l*Bsz*HID];
    const float* Hr = &g_H[(size_t)r*Bsz*HID];

    for (int kt = 0; kt < HID; kt += 16) {
#pragma unroll
        for (int i = 0; i < 2; i++) {
            int idx = t + i * 512;
            int row = idx >> 4, kk = idx & 15;
            int ga = (b0+row)*HID + kt + kk;
            hs[kk][row] = 0.5f*(Hl[ga] + Hr[ga]);
        }
#pragma unroll
        for (int i = 0; i < 12; i++) {
            int idx = t + i * 512;
            int kk = idx / G3, c = idx - kk*G3;
            Ws[kk][c] = g_WhhT[(kt+kk)*G3 + c];
        }
        __syncthreads();
#pragma unroll
        for (int kk = 0; kk < 16; kk++) {
            float4 a  = *(const float4*)&hs[kk][row0];
            float4 wr = *(const float4*)&Ws[kk][col0];
            float4 wz = *(const float4*)&Ws[kk][128 + col0];
            float4 wn = *(const float4*)&Ws[kk][256 + col0];
            float av[4] = {a.x,a.y,a.z,a.w};
            float vr[4] = {wr.x,wr.y,wr.z,wr.w};
            float vz[4] = {wz.x,wz.y,wz.z,wz.w};
            float vn[4] = {wn.x,wn.y,wn.z,wn.w};
#pragma unroll
            for (int i = 0; i < 4; i++)
#pragma unroll
                for (int j = 0; j < 4; j++) {
                    aR[i][j] += av[i]*vr[j];
                    aZ[i][j] += av[i]*vz[j];
                    aN[i][j] += av[i]*vn[j];
                }
        }
        __syncthreads();
    }

#pragma unroll
    for (int i = 0; i < 4; i++) {
        int b = b0 + row0 + i;
        size_t gib = ((size_t)node*Bsz + b)*G3;
        size_t hb  = ((size_t)node*Bsz + b)*HID;
        int ha = b * HID;
#pragma unroll
        for (int j = 0; j < 4; j++) {
            int g = col0 + j;
            float hv = 0.5f*(Hl[ha+g] + Hr[ha+g]);
            float rg = 1.f/(1.f + expf(-(g_gi[gib + g]       + aR[i][j] + bhh[g])));
            float zg = 1.f/(1.f + expf(-(g_gi[gib + 128 + g] + aZ[i][j] + bhh[128+g])));
            float ng = tanhf(g_gi[gib + 256 + g] + rg*(aN[i][j] + bhh[256+g]));
            g_H[hb + g] = (1.f - zg)*ng + zg*hv;
        }
    }
}

// ---------------- heads ----------------
__global__ __launch_bounds__(128) void k_heads(const float* __restrict__ W2a, const float* __restrict__ b2a,
                                               const float* __restrict__ W3a, const float* __restrict__ b3a,
                                               const float* __restrict__ Woa, const float* __restrict__ boa,
                                               const float* __restrict__ W2b, const float* __restrict__ b2b,
                                               const float* __restrict__ W3b, const float* __restrict__ b3b,
                                               const float* __restrict__ Wob, const float* __restrict__ bob,
                                               float* __restrict__ out) {
    const int b = blockIdx.x, head = blockIdx.y, t = threadIdx.x;
    const float* W2 = head ? W2b : W2a;  const float* b2 = head ? b2b : b2a;
    const float* W3 = head ? W3b : W3a;  const float* b3 = head ? b3b : b3a;
    const float* Wo = head ? Wob : Woa;  const float* bo = head ? bob : boa;

    __shared__ float s0[128], s1[128], red[4];
    s0[t] = g_H[((size_t)(Nn-1)*Bsz + b)*HID + t];
    __syncthreads();
    float acc = b2[t];
#pragma unroll 8
    for (int k = 0; k < 128; k++) acc += s0[k] * W2[t*128 + k];
    s1[t] = fmaxf(acc, 0.f);
    __syncthreads();
    acc = b3[t];
#pragma unroll 8
    for (int k = 0; k < 128; k++) acc += s1[k] * W3[t*128 + k];
    float h2 = fmaxf(acc, 0.f);
    float v = h2 * Wo[t];
#pragma unroll
    for (int off = 16; off; off >>= 1) v += __shfl_down_sync(0xffffffffu, v, off);
    if ((t & 31) == 0) red[t >> 5] = v;
    __syncthreads();
    if (t == 0) {
        float s = red[0] + red[1] + red[2] + red[3] + bo[0];
        out[head * Bsz + b] = 1.f/(1.f + expf(-s));
    }
}

// ---------------- launcher ----------------
extern "C" void kernel_launch(void* const* d_in, const int* in_sizes, int n_in,
                              void* d_out, int out_size) {
    const float* op    = (const float*)d_in[0];
    const float* ex    = (const float*)d_in[1];
    const float* p1    = (const float*)d_in[2];
    const float* p2    = (const float*)d_in[3];
    const int*   c1p   = (const int*)  d_in[4];
    const int*   c2p   = (const int*)  d_in[5];
    const int*   hc    = (const int*)  d_in[6];
    const float* bmp   = (const float*)d_in[7];
    const int*   li    = (const int*)  d_in[8];
    const int*   ri    = (const int*)  d_in[9];
    const float* Wop   = (const float*)d_in[10];
    const float* bop   = (const float*)d_in[11];
    const float* Wpred = (const float*)d_in[12];
    const float* bpred = (const float*)d_in[13];
    const float* Wbm   = (const float*)d_in[14];
    const float* bbm   = (const float*)d_in[15];
    const float* Wih   = (const float*)d_in[16];
    const float* bih   = (const float*)d_in[17];
    const float* Whh   = (const float*)d_in[18];
    const float* bhh   = (const float*)d_in[19];
    const float* W2t1  = (const float*)d_in[20];
    const float* b2t1  = (const float*)d_in[21];
    const float* W3t1  = (const float*)d_in[22];
    const float* b3t1  = (const float*)d_in[23];
    const float* Wot1  = (const float*)d_in[24];
    const float* bot1  = (const float*)d_in[25];
    const float* W2t2  = (const float*)d_in[26];
    const float* b2t2  = (const float*)d_in[27];
    const float* W3t2  = (const float*)d_in[28];
    const float* b3t2  = (const float*)d_in[29];
    const float* Wot2  = (const float*)d_in[30];
    const float* bot2  = (const float*)d_in[31];
    float* out = (float*)d_out;

    k_prep<<<(128*96 + G3*HID + 255)/256, 256>>>(Wop, Whh);
    k_depth<<<1, 1>>>(li);
    k_opemb<<<Rr/64, 256>>>(op, ex, bop);
    k_pred_mma<<<dim3((Rr*8)/128, 2), 256>>>(p1, p2, c1p, c2p, Wpred, bpred);
    k_bm_mma<<<Rr/128, 256>>>(bmp, Wbm, bbm, hc);
    k_gi_mma<<<dim3(Rr/128, 3), 256>>>(Wih, bih);
    for (int lvl = 1; lvl <= 6; lvl++)
        k_recur<<<dim3(Bsz/64, Nn), 512>>>(li, ri, bhh, lvl);
    k_heads<<<dim3(Bsz, 2), 128>>>(W2t1, b2t1, W3t1, b3t1, Wot1, bot1,
                                   W2t2, b2t2, W3t2, b3t2, Wot2, bot2, out);
}

// round 4
// speedup vs baseline: 1.8779x; 1.0612x over previous
#include <cuda_runtime.h>
#include <cuda_bf16.h>
#include <math.h>

#define Bsz 1024
#define Nn  63
#define Rr  (Bsz*Nn)      // 64512
#define HID 128
#define G3  384
#define XK  512
#define BMV 1000

#define SMW 36            // words per smem row (32 data + 4 pad)
#define TILEW (128*SMW)   // words per 128-row tile
#define DSMEM_BYTES (4*TILEW*4)   // 2 buffers x (A+B) tiles

// ---------------- scratch ----------------
__device__ float g_x [(size_t)Rr*XK];        // [r][512] concat(opemb,c1,c2,bm)
__device__ float g_gi[(size_t)Nn*Bsz*G3];    // [n][b][384]
__device__ float g_gh[(size_t)Nn*Bsz*G3];    // [n][b][384] hidden-gate pre-acts
__device__ float g_H [(size_t)Nn*Bsz*HID];   // [n][b][128]
__device__ float g_WopT [96*128];            // [k][h]
__device__ int   g_levels[8*32];
__device__ int   g_levcnt[8];

// ---------------- prep ----------------
__global__ void k_prep(const float* __restrict__ Wop) {
    int i = blockIdx.x * blockDim.x + threadIdx.x;
    if (i < 128*96) { int r=i/96, c=i-r*96; g_WopT[c*128+r] = Wop[i]; }
}

__global__ void k_depth(const int* __restrict__ li) {
    if (threadIdx.x == 0 && blockIdx.x == 0) {
        int depth[Nn];
        for (int d = 0; d < 8; d++) g_levcnt[d] = 0;
        for (int i = 0; i < Nn; i++) {
            int l = li[i];
            depth[i] = (l < 0) ? 1 : (depth[l] + 1);
            int d = depth[i];
            g_levels[d*32 + g_levcnt[d]] = i;
            g_levcnt[d]++;
        }
    }
}

// ================= bf16 MMA machinery =================
__device__ __forceinline__ unsigned pack2(float lo, float hi) {
    __nv_bfloat162 h = __floats2bfloat162_rn(lo, hi);
    return *(unsigned*)&h;
}

__device__ __forceinline__ void mma_bf16(float c[4], unsigned a0, unsigned a1,
                                         unsigned a2, unsigned a3,
                                         unsigned b0, unsigned b1) {
    asm volatile("mma.sync.aligned.m16n8k16.row.col.f32.bf16.bf16.f32 "
                 "{%0,%1,%2,%3}, {%4,%5,%6,%7}, {%8,%9}, {%0,%1,%2,%3};"
                 : "+f"(c[0]), "+f"(c[1]), "+f"(c[2]), "+f"(c[3])
                 : "r"(a0), "r"(a1), "r"(a2), "r"(a3), "r"(b0), "r"(b1));
}

// stage 128 rows x 64 k-elements (32 words) as bf16 pairs; A2 != null -> 0.5*(A+A2)
__device__ __forceinline__ void stage_bf16(unsigned* S, const float* __restrict__ A,
                                           const float* __restrict__ A2,
                                           int ld, int rbase, int kt, int Ktot, int t) {
    const int tr = t >> 3, wg = t & 7;
#pragma unroll
    for (int p = 0; p < 4; p++) {
        int row = p * 32 + tr;
        size_t off = (size_t)(rbase + row) * ld + kt + wg * 8;
        int k0 = kt + wg * 8;
        uint4 w;
        if (k0 + 8 <= Ktot) {
            float4 v0 = *(const float4*)(A + off);
            float4 v1 = *(const float4*)(A + off + 4);
            if (A2) {
                float4 u0 = *(const float4*)(A2 + off);
                float4 u1 = *(const float4*)(A2 + off + 4);
                v0.x = 0.5f*(v0.x+u0.x); v0.y = 0.5f*(v0.y+u0.y);
                v0.z = 0.5f*(v0.z+u0.z); v0.w = 0.5f*(v0.w+u0.w);
                v1.x = 0.5f*(v1.x+u1.x); v1.y = 0.5f*(v1.y+u1.y);
                v1.z = 0.5f*(v1.z+u1.z); v1.w = 0.5f*(v1.w+u1.w);
            }
            w.x = pack2(v0.x, v0.y); w.y = pack2(v0.z, v0.w);
            w.z = pack2(v1.x, v1.y); w.w = pack2(v1.z, v1.w);
        } else {
            float f[8];
#pragma unroll
            for (int i = 0; i < 8; i++) {
                float v = 0.f;
                if (k0 + i < Ktot) {
                    v = A[off + i];
                    if (A2) v = 0.5f*(v + A2[off + i]);
                }
                f[i] = v;
            }
            w.x = pack2(f[0], f[1]); w.y = pack2(f[2], f[3]);
            w.z = pack2(f[4], f[5]); w.w = pack2(f[6], f[7]);
        }
        *(uint4*)&S[row * SMW + wg * 4] = w;
    }
}

// one k16 step: 2 m-tiles x 8 n-tiles into c[2][8][4]; w0 = word offset of step
__device__ __forceinline__ void mma_step16(const unsigned* As, const unsigned* Bs,
                                           int w0, int wm, int wn, int lane,
                                           float c[2][8][4]) {
    const int qr = lane >> 2, qc = lane & 3;
    unsigned a[2][4];
#pragma unroll
    for (int mt = 0; mt < 2; mt++) {
        int m = wm * 32 + mt * 16 + qr;
        a[mt][0] = As[m * SMW + w0 + qc];
        a[mt][1] = As[(m + 8) * SMW + w0 + qc];
        a[mt][2] = As[m * SMW + w0 + qc + 4];
        a[mt][3] = As[(m + 8) * SMW + w0 + qc + 4];
    }
#pragma unroll
    for (int nt = 0; nt < 8; nt++) {
        int n = wn * 64 + nt * 8 + qr;
        unsigned b0 = Bs[n * SMW + w0 + qc];
        unsigned b1 = Bs[n * SMW + w0 + qc + 4];
#pragma unroll
        for (int mt = 0; mt < 2; mt++)
            mma_bf16(c[mt][nt], a[mt][0], a[mt][1], a[mt][2], a[mt][3], b0, b1);
    }
}

// C[128x128] = A(avg A2)[rbase:+128, :Ktot] @ B[cbase:+128, :Ktot]^T, double-buffered
__device__ __forceinline__ void mm_bf16(const float* __restrict__ A,
                                        const float* __restrict__ A2, int lda,
                                        const float* __restrict__ B, int ldb,
                                        int Ktot, int rbase, int cbase,
                                        unsigned* SM, int t, int wm, int wn, int lane,
                                        float c[2][8][4]) {
#pragma unroll
    for (int mt = 0; mt < 2; mt++)
#pragma unroll
        for (int nt = 0; nt < 8; nt++)
#pragma unroll
            for (int j = 0; j < 4; j++) c[mt][nt][j] = 0.f;

    unsigned* SA[2] = {SM,             SM + 2*TILEW};
    unsigned* SB[2] = {SM + TILEW,     SM + 3*TILEW};
    const int nc = (Ktot + 63) >> 6;
    stage_bf16(SA[0], A, A2, lda, rbase, 0, Ktot, t);
    stage_bf16(SB[0], B, (const float*)0, ldb, cbase, 0, Ktot, t);
    __syncthreads();
    for (int ch = 0; ch < nc; ch++) {
        int cur = ch & 1;
        if (ch + 1 < nc) {
            stage_bf16(SA[cur^1], A, A2, lda, rbase, (ch+1) << 6, Ktot, t);
            stage_bf16(SB[cur^1], B, (const float*)0, ldb, cbase, (ch+1) << 6, Ktot, t);
        }
#pragma unroll
        for (int ks = 0; ks < 4; ks++) mma_step16(SA[cur], SB[cur], ks * 8, wm, wn, lane, c);
        __syncthreads();
    }
}

// ---------------- pred (bf16): min over P=8, per cond ----------------
__global__ __launch_bounds__(256) void k_pred_mma(const float* __restrict__ p1,
                                                  const float* __restrict__ p2,
                                                  const int* __restrict__ c1p,
                                                  const int* __restrict__ c2p,
                                                  const float* __restrict__ Wpred,
                                                  const float* __restrict__ bpred) {
    extern __shared__ unsigned dsm[];
    const float* preds = blockIdx.y ? p2 : p1;
    const int*   cond  = blockIdx.y ? c2p : c1p;
    const int xoff = blockIdx.y ? 256 : 128;
    const int t = threadIdx.x, lane = t & 31, warp = t >> 5;
    const int wm = warp >> 1, wn = warp & 1;
    const int rbase = blockIdx.x * 128;
    float c[2][8][4];
    mm_bf16(preds, (const float*)0, 64, Wpred, 64, 64, rbase, 0, dsm, t, wm, wn, lane, c);

    const int qc = lane & 3;
#pragma unroll
    for (int mt = 0; mt < 2; mt++)
#pragma unroll
        for (int nt = 0; nt < 8; nt++)
#pragma unroll
            for (int j = 0; j < 4; j++) {
                float v = c[mt][nt][j];
                v = fminf(v, __shfl_xor_sync(0xffffffffu, v, 4));
                v = fminf(v, __shfl_xor_sync(0xffffffffu, v, 8));
                v = fminf(v, __shfl_xor_sync(0xffffffffu, v, 16));
                c[mt][nt][j] = v;
            }
    if (lane < 4) {
#pragma unroll
        for (int mt = 0; mt < 2; mt++) {
            int or0 = (rbase + wm * 32 + mt * 16) >> 3;
#pragma unroll
            for (int nt = 0; nt < 8; nt++)
#pragma unroll
                for (int j = 0; j < 4; j++) {
                    int orow = or0 + ((j >= 2) ? 1 : 0);
                    int col = wn * 64 + nt * 8 + qc * 2 + (j & 1);
                    float val = (c[mt][nt][j] + bpred[col]) * (float)cond[orow];
                    g_x[(size_t)orow * XK + xoff + col] = val;
                }
        }
    }
}

// ---------------- bitmap (bf16) ----------------
__global__ __launch_bounds__(256) void k_bm_mma(const float* __restrict__ bm,
                                                const float* __restrict__ Wbm,
                                                const float* __restrict__ bbm,
                                                const int* __restrict__ hc) {
    extern __shared__ unsigned dsm[];
    const int t = threadIdx.x, lane = t & 31, warp = t >> 5;
    const int wm = warp >> 1, wn = warp & 1;
    const int rbase = blockIdx.x * 128;
    float c[2][8][4];
    mm_bf16(bm, (const float*)0, BMV, Wbm, BMV, BMV, rbase, 0, dsm, t, wm, wn, lane, c);

    const int qr = lane >> 2, qc = lane & 3;
#pragma unroll
    for (int mt = 0; mt < 2; mt++)
#pragma unroll
        for (int j = 0; j < 4; j++) {
            int r = rbase + wm * 32 + mt * 16 + qr + ((j >= 2) ? 8 : 0);
            float has = (float)hc[r];
#pragma unroll
            for (int nt = 0; nt < 8; nt++) {
                int col = wn * 64 + nt * 8 + qc * 2 + (j & 1);
                g_x[(size_t)r * XK + 384 + col] = (c[mt][nt][j] + bbm[col]) * has;
            }
        }
}

// ---------------- gi (bf16): g_gi[n][b][g] = x @ Wih^T + b_ih ----------------
__global__ __launch_bounds__(256) void k_gi_mma(const float* __restrict__ Wih,
                                                const float* __restrict__ bih) {
    extern __shared__ unsigned dsm[];
    const int t = threadIdx.x, lane = t & 31, warp = t >> 5;
    const int wm = warp >> 1, wn = warp & 1;
    const int rbase = blockIdx.x * 128;
    const int cbase = blockIdx.y * 128;
    float c[2][8][4];
    mm_bf16(g_x, (const float*)0, XK, Wih, XK, XK, rbase, cbase, dsm, t, wm, wn, lane, c);

    const int qr = lane >> 2, qc = lane & 3;
#pragma unroll
    for (int mt = 0; mt < 2; mt++)
#pragma unroll
        for (int j = 0; j < 4; j++) {
            int r = rbase + wm * 32 + mt * 16 + qr + ((j >= 2) ? 8 : 0);
            int n = r % Nn, b = r / Nn;
            size_t obase = ((size_t)n * Bsz + b) * G3;
#pragma unroll
            for (int nt = 0; nt < 8; nt++) {
                int g = cbase + wn * 64 + nt * 8 + qc * 2 + (j & 1);
                g_gi[obase + g] = c[mt][nt][j] + bih[g];
            }
        }
}

// ---------------- gh (bf16): per-level gh[node][b][g] = 0.5(Hl+Hr) @ Whh^T ----------------
__global__ __launch_bounds__(256) void k_gh_mma(const int* __restrict__ li,
                                                const int* __restrict__ ri,
                                                const float* __restrict__ Whh,
                                                int level) {
    extern __shared__ unsigned dsm[];
    const int slot = blockIdx.z;
    if (slot >= g_levcnt[level]) return;
    const int node = g_levels[level*32 + slot];
    const int l = li[node], r = ri[node];
    const int t = threadIdx.x, lane = t & 31, warp = t >> 5;
    const int wm = warp >> 1, wn = warp & 1;
    const int rbase = blockIdx.x * 128;   // b rows
    const int cbase = blockIdx.y * 128;   // g cols
    const float* Hl = &g_H[(size_t)l * Bsz * HID];
    const float* Hr = &g_H[(size_t)r * Bsz * HID];
    float c[2][8][4];
    mm_bf16(Hl, Hr, HID, Whh, HID, HID, rbase, cbase, dsm, t, wm, wn, lane, c);

    const int qr = lane >> 2, qc = lane & 3;
#pragma unroll
    for (int mt = 0; mt < 2; mt++)
#pragma unroll
        for (int j = 0; j < 4; j++) {
            int b = rbase + wm * 32 + mt * 16 + qr + ((j >= 2) ? 8 : 0);
            size_t obase = ((size_t)node * Bsz + b) * G3;
#pragma unroll
            for (int nt = 0; nt < 8; nt++) {
                int g = cbase + wn * 64 + nt * 8 + qc * 2 + (j & 1);
                g_gh[obase + g] = c[mt][nt][j];
            }
        }
}

// ---------------- gate: elementwise GRU cell per level ----------------
__global__ __launch_bounds__(256) void k_gate(const int* __restrict__ li,
                                              const int* __restrict__ ri,
                                              const float* __restrict__ bhh,
                                              int level) {
    const int slot = blockIdx.y;
    if (slot >= g_levcnt[level]) return;
    const int node = g_levels[level*32 + slot];
    const int l = li[node], r = ri[node];
    const int idx = blockIdx.x * 256 + threadIdx.x;   // 0 .. 131071
    const int b = idx >> 7, g = idx & 127;
    const size_t gib = ((size_t)node * Bsz + b) * G3;
    const float br = bhh[g], bz = bhh[128+g], bn = bhh[256+g];
    float hv, ghr, ghz, ghn;
    if (l < 0) {
        hv = 0.f; ghr = br; ghz = bz; ghn = bn;
    } else {
        hv = 0.5f * (g_H[(size_t)l*Bsz*HID + b*HID + g] + g_H[(size_t)r*Bsz*HID + b*HID + g]);
        ghr = g_gh[gib + g] + br;
        ghz = g_gh[gib + 128 + g] + bz;
        ghn = g_gh[gib + 256 + g] + bn;
    }
    float rg = 1.f/(1.f + expf(-(g_gi[gib + g] + ghr)));
    float zg = 1.f/(1.f + expf(-(g_gi[gib + 128 + g] + ghz)));
    float ng = tanhf(g_gi[gib + 256 + g] + rg * ghn);
    g_H[((size_t)node * Bsz + b) * HID + g] = (1.f - zg) * ng + zg * hv;
}

// ---------------- opemb (fp32, small) ----------------
__global__ __launch_bounds__(256) void k_opemb(const float* __restrict__ op,
                                               const float* __restrict__ ex,
                                               const float* __restrict__ bop) {
    __shared__ float As[16][68];
    __shared__ float Bs[16][128];
    const int t = threadIdx.x;
    const int rbase = blockIdx.x * 64;
    const int ty = t >> 5, tx = t & 31;
    const int row0 = ty * 8, col0 = tx * 4;
    float acc[8][4];
#pragma unroll
    for (int i = 0; i < 8; i++)
#pragma unroll
        for (int j = 0; j < 4; j++) acc[i][j] = 0.f;

    for (int kt = 0; kt < 96; kt += 16) {
#pragma unroll
        for (int i = 0; i < 4; i++) {
            int idx = t + i * 256;
            int row = idx >> 4, kk = idx & 15;
            int k = kt + kk;
            As[kk][row] = (k < 32) ? op[(size_t)(rbase+row)*32 + k]
                                   : ex[(size_t)(rbase+row)*64 + (k-32)];
        }
#pragma unroll
        for (int i = 0; i < 8; i++) {
            int idx = t + i * 256;
            int kk = idx >> 7, c = idx & 127;
            Bs[kk][c] = g_WopT[(kt+kk)*128 + c];
        }
        __syncthreads();
#pragma unroll
        for (int kk = 0; kk < 16; kk++) {
            float4 a0 = *(const float4*)&As[kk][row0];
            float4 a1 = *(const float4*)&As[kk][row0+4];
            float4 b  = *(const float4*)&Bs[kk][col0];
            float a[8] = {a0.x,a0.y,a0.z,a0.w,a1.x,a1.y,a1.z,a1.w};
            float bb[4]= {b.x,b.y,b.z,b.w};
#pragma unroll
            for (int i = 0; i < 8; i++)
#pragma unroll
                for (int j = 0; j < 4; j++) acc[i][j] += a[i]*bb[j];
        }
        __syncthreads();
    }
#pragma unroll
    for (int i = 0; i < 8; i++) {
        int r = rbase + row0 + i;
#pragma unroll
        for (int j = 0; j < 4; j++)
            g_x[(size_t)r*XK + col0 + j] = acc[i][j] + bop[col0+j];
    }
}

// ---------------- heads ----------------
__global__ __launch_bounds__(128) void k_heads(const float* __restrict__ W2a, const float* __restrict__ b2a,
                                               const float* __restrict__ W3a, const float* __restrict__ b3a,
                                               const float* __restrict__ Woa, const float* __restrict__ boa,
                                               const float* __restrict__ W2b, const float* __restrict__ b2b,
                                               const float* __restrict__ W3b, const float* __restrict__ b3b,
                                               const float* __restrict__ Wob, const float* __restrict__ bob,
                                               float* __restrict__ out) {
    const int b = blockIdx.x, head = blockIdx.y, t = threadIdx.x;
    const float* W2 = head ? W2b : W2a;  const float* b2 = head ? b2b : b2a;
    const float* W3 = head ? W3b : W3a;  const float* b3 = head ? b3b : b3a;
    const float* Wo = head ? Wob : Woa;  const float* bo = head ? bob : boa;

    __shared__ float s0[128], s1[128], red[4];
    s0[t] = g_H[((size_t)(Nn-1)*Bsz + b)*HID + t];
    __syncthreads();
    float acc = b2[t];
#pragma unroll 8
    for (int k = 0; k < 128; k++) acc += s0[k] * W2[t*128 + k];
    s1[t] = fmaxf(acc, 0.f);
    __syncthreads();
    acc = b3[t];
#pragma unroll 8
    for (int k = 0; k < 128; k++) acc += s1[k] * W3[t*128 + k];
    float h2 = fmaxf(acc, 0.f);
    float v = h2 * Wo[t];
#pragma unroll
    for (int off = 16; off; off >>= 1) v += __shfl_down_sync(0xffffffffu, v, off);
    if ((t & 31) == 0) red[t >> 5] = v;
    __syncthreads();
    if (t == 0) {
        float s = red[0] + red[1] + red[2] + red[3] + bo[0];
        out[head * Bsz + b] = 1.f/(1.f + expf(-s));
    }
}

// ---------------- launcher ----------------
extern "C" void kernel_launch(void* const* d_in, const int* in_sizes, int n_in,
                              void* d_out, int out_size) {
    const float* op    = (const float*)d_in[0];
    const float* ex    = (const float*)d_in[1];
    const float* p1    = (const float*)d_in[2];
    const float* p2    = (const float*)d_in[3];
    const int*   c1p   = (const int*)  d_in[4];
    const int*   c2p   = (const int*)  d_in[5];
    const int*   hc    = (const int*)  d_in[6];
    const float* bmp   = (const float*)d_in[7];
    const int*   li    = (const int*)  d_in[8];
    const int*   ri    = (const int*)  d_in[9];
    const float* Wop   = (const float*)d_in[10];
    const float* bop   = (const float*)d_in[11];
    const float* Wpred = (const float*)d_in[12];
    const float* bpred = (const float*)d_in[13];
    const float* Wbm   = (const float*)d_in[14];
    const float* bbm   = (const float*)d_in[15];
    const float* Wih   = (const float*)d_in[16];
    const float* bih   = (const float*)d_in[17];
    const float* Whh   = (const float*)d_in[18];
    const float* bhh   = (const float*)d_in[19];
    const float* W2t1  = (const float*)d_in[20];
    const float* b2t1  = (const float*)d_in[21];
    const float* W3t1  = (const float*)d_in[22];
    const float* b3t1  = (const float*)d_in[23];
    const float* Wot1  = (const float*)d_in[24];
    const float* bot1  = (const float*)d_in[25];
    const float* W2t2  = (const float*)d_in[26];
    const float* b2t2  = (const float*)d_in[27];
    const float* W3t2  = (const float*)d_in[28];
    const float* b3t2  = (const float*)d_in[29];
    const float* Wot2  = (const float*)d_in[30];
    const float* bot2  = (const float*)d_in[31];
    float* out = (float*)d_out;

    static int smem_set = 0;
    if (!smem_set) {
        cudaFuncSetAttribute(k_pred_mma, cudaFuncAttributeMaxDynamicSharedMemorySize, DSMEM_BYTES);
        cudaFuncSetAttribute(k_bm_mma,   cudaFuncAttributeMaxDynamicSharedMemorySize, DSMEM_BYTES);
        cudaFuncSetAttribute(k_gi_mma,   cudaFuncAttributeMaxDynamicSharedMemorySize, DSMEM_BYTES);
        cudaFuncSetAttribute(k_gh_mma,   cudaFuncAttributeMaxDynamicSharedMemorySize, DSMEM_BYTES);
        smem_set = 1;
    }

    k_prep<<<(128*96 + 255)/256, 256>>>(Wop);
    k_depth<<<1, 1>>>(li);
    k_opemb<<<Rr/64, 256>>>(op, ex, bop);
    k_pred_mma<<<dim3((Rr*8)/128, 2), 256, DSMEM_BYTES>>>(p1, p2, c1p, c2p, Wpred, bpred);
    k_bm_mma<<<Rr/128, 256, DSMEM_BYTES>>>(bmp, Wbm, bbm, hc);
    k_gi_mma<<<dim3(Rr/128, 3), 256, DSMEM_BYTES>>>(Wih, bih);
    k_gate<<<dim3(512, 32), 256>>>(li, ri, bhh, 1);
    for (int lvl = 2; lvl <= 6; lvl++) {
        k_gh_mma<<<dim3(8, 3, 16), 256, DSMEM_BYTES>>>(li, ri, Whh, lvl);
        k_gate<<<dim3(512, 16), 256>>>(li, ri, bhh, lvl);
    }
    k_heads<<<dim3(Bsz, 2), 128>>>(W2t1, b2t1, W3t1, b3t1, Wot1, bot1,
                                   W2t2, b2t2, W3t2, b3t2, Wot2, bot2, out);
}

// round 6
// speedup vs baseline: 2.2355x; 1.1904x over previous
#include <cuda_runtime.h>
#include <cuda_bf16.h>
#include <math.h>

#define Bsz 1024
#define Nn  63
#define Rr  (Bsz*Nn)      // 64512
#define HID 128
#define G3  384
#define XK  512
#define BMV 1000

#define SMW 36            // words per smem row (32 data words = 64 bf16 + 4 pad)
#define TILEW (128*SMW)   // words per 128-row tile
#define DSMEM_BYTES (4*TILEW*4)   // 2 buffers x (A+B) tiles = 72KB
#define GH_SMEM (2*TILEW*4)       // 1 buffer x (A+B) = 36KB

#define NP1 ((size_t)Rr*8*64)     // 33030144 elems
#define NBM ((size_t)Rr*BMV)      // 64512000 elems
#define NX  ((size_t)Rr*XK)       // 33030144 elems

// ---------------- aliased scratch pool (phase-disjoint lifetimes) ----------------
// region A [0, 132MB):   p1b (66MB) + p2b (66MB)   [cvt -> pred]
//                        then g_gi (99MB, float)    [gi -> gates]
// region B [132, 261MB): bmb (129MB)               [cvt -> bm]
//                        then g_gh (99MB, float)    [recurrence]
// region C [261, 327MB): xb (66MB)                 [opemb/pred/bm -> gi]
// region D [327, 360MB): g_H (33MB, float)         [recurrence -> heads]
#define OFF_P1B ((size_t)0)
#define OFF_P2B ((size_t)66060288)
#define OFF_GI  ((size_t)0)
#define OFF_BMB ((size_t)132120576)
#define OFF_GH  ((size_t)132120576)
#define OFF_XB  ((size_t)261144576)
#define OFF_H   ((size_t)327204864)
#define POOL_BYTES ((size_t)360235008)

__device__ __align__(128) unsigned char g_pool[POOL_BYTES];

#define PTR_P1B ((__nv_bfloat16*)(g_pool + OFF_P1B))
#define PTR_P2B ((__nv_bfloat16*)(g_pool + OFF_P2B))
#define PTR_GI  ((float*)(g_pool + OFF_GI))
#define PTR_BMB ((__nv_bfloat16*)(g_pool + OFF_BMB))
#define PTR_GH  ((float*)(g_pool + OFF_GH))
#define PTR_XB  ((__nv_bfloat16*)(g_pool + OFF_XB))
#define PTR_H   ((float*)(g_pool + OFF_H))

__device__ float g_WopT [96*128];
__device__ __nv_bfloat16 g_Wpb  [128*64];
__device__ __nv_bfloat16 g_Wbmb [128*BMV];
__device__ __nv_bfloat16 g_Wihb [G3*XK];
__device__ __nv_bfloat16 g_Whhb [G3*HID];
__device__ int g_levels[8*32];
__device__ int g_levcnt[8];

// ---------------- prep: transpose Wop (fp32) + convert weights to bf16 ----------------
__global__ void k_prep(const float* __restrict__ Wop, const float* __restrict__ Wpred,
                       const float* __restrict__ Wbm, const float* __restrict__ Wih,
                       const float* __restrict__ Whh) {
    int i = blockIdx.x * blockDim.x + threadIdx.x;
    if (i < 128*96) { int r=i/96, c=i-r*96; g_WopT[c*128+r] = Wop[i]; return; }
    i -= 128*96;
    if (i < 128*64)   { g_Wpb[i]   = __float2bfloat16(Wpred[i]); return; }
    i -= 128*64;
    if (i < 128*BMV)  { g_Wbmb[i]  = __float2bfloat16(Wbm[i]);   return; }
    i -= 128*BMV;
    if (i < G3*XK)    { g_Wihb[i]  = __float2bfloat16(Wih[i]);   return; }
    i -= G3*XK;
    if (i < G3*HID)   { g_Whhb[i]  = __float2bfloat16(Whh[i]);   return; }
}

__global__ void k_depth(const int* __restrict__ li) {
    if (threadIdx.x == 0 && blockIdx.x == 0) {
        int depth[Nn];
        for (int d = 0; d < 8; d++) g_levcnt[d] = 0;
        for (int i = 0; i < Nn; i++) {
            int l = li[i];
            depth[i] = (l < 0) ? 1 : (depth[l] + 1);
            int d = depth[i];
            g_levels[d*32 + g_levcnt[d]] = i;
            g_levcnt[d]++;
        }
    }
}

// ---------------- bulk fp32 -> bf16 convert ----------------
__global__ __launch_bounds__(256) void k_cvt(const float* __restrict__ s,
                                             __nv_bfloat16* __restrict__ d, size_t n) {
    size_t i = ((size_t)blockIdx.x * 256 + threadIdx.x) * 4;
    size_t stride = (size_t)gridDim.x * 256 * 4;
    for (; i < n; i += stride) {
        float4 v = *(const float4*)(s + i);
        __nv_bfloat162 lo = __floats2bfloat162_rn(v.x, v.y);
        __nv_bfloat162 hi = __floats2bfloat162_rn(v.z, v.w);
        *(uint2*)(d + i) = make_uint2(*(unsigned*)&lo, *(unsigned*)&hi);
    }
}

// ================= bf16 MMA machinery =================
__device__ __forceinline__ unsigned pack2(float lo, float hi) {
    __nv_bfloat162 h = __floats2bfloat162_rn(lo, hi);
    return *(unsigned*)&h;
}

__device__ __forceinline__ void mma_bf16(float c[4], unsigned a0, unsigned a1,
                                         unsigned a2, unsigned a3,
                                         unsigned b0, unsigned b1) {
    asm volatile("mma.sync.aligned.m16n8k16.row.col.f32.bf16.bf16.f32 "
                 "{%0,%1,%2,%3}, {%4,%5,%6,%7}, {%8,%9}, {%0,%1,%2,%3};"
                 : "+f"(c[0]), "+f"(c[1]), "+f"(c[2]), "+f"(c[3])
                 : "r"(a0), "r"(a1), "r"(a2), "r"(a3), "r"(b0), "r"(b1));
}

__device__ __forceinline__ void ldsm4(unsigned addr, unsigned &r0, unsigned &r1,
                                      unsigned &r2, unsigned &r3) {
    asm volatile("ldmatrix.sync.aligned.m8n8.x4.shared.b16 {%0,%1,%2,%3}, [%4];"
                 : "=r"(r0), "=r"(r1), "=r"(r2), "=r"(r3) : "r"(addr));
}

__device__ __forceinline__ void cp16(unsigned dst, const void* src, int src_bytes) {
    asm volatile("cp.async.cg.shared.global [%0], [%1], 16, %2;\n"
                 :: "r"(dst), "l"(src), "r"(src_bytes));
}
__device__ __forceinline__ void cp_commit() {
    asm volatile("cp.async.commit_group;\n" ::: "memory");
}
template<int N> __device__ __forceinline__ void cp_wait() {
    asm volatile("cp.async.wait_group %0;\n" :: "n"(N) : "memory");
}

// per-lane ldmatrix byte offsets within a tile
__device__ __forceinline__ void frag_offs(int lane, int wm, int wn,
                                          unsigned aoff[2], unsigned boff[4]) {
    int g = lane >> 3, ri = lane & 7;
#pragma unroll
    for (int mt = 0; mt < 2; mt++) {
        int row = wm*32 + mt*16 + (g & 1)*8 + ri;
        aoff[mt] = row * (SMW*4) + (g >> 1) * 16;
    }
#pragma unroll
    for (int p = 0; p < 4; p++) {
        int row = wn*64 + p*16 + (g >> 1)*8 + ri;
        boff[p] = row * (SMW*4) + (g & 1) * 16;
    }
}

// consume one 64-k chunk: 4 k16 steps
__device__ __forceinline__ void mma_chunk(unsigned abase, unsigned bbase,
                                          const unsigned aoff[2], const unsigned boff[4],
                                          float c[2][8][4]) {
#pragma unroll
    for (int ks = 0; ks < 4; ks++) {
        unsigned a[2][4];
#pragma unroll
        for (int mt = 0; mt < 2; mt++)
            ldsm4(abase + aoff[mt] + ks*32, a[mt][0], a[mt][1], a[mt][2], a[mt][3]);
#pragma unroll
        for (int p = 0; p < 4; p++) {
            unsigned b0, b1, b2, b3;
            ldsm4(bbase + boff[p] + ks*32, b0, b1, b2, b3);
            mma_bf16(c[0][2*p],   a[0][0], a[0][1], a[0][2], a[0][3], b0, b1);
            mma_bf16(c[1][2*p],   a[1][0], a[1][1], a[1][2], a[1][3], b0, b1);
            mma_bf16(c[0][2*p+1], a[0][0], a[0][1], a[0][2], a[0][3], b2, b3);
            mma_bf16(c[1][2*p+1], a[1][0], a[1][1], a[1][2], a[1][3], b2, b3);
        }
    }
}

// async stage: 128 rows x 64 k (bf16 source) into tile at smem byte addr sbase
__device__ __forceinline__ void stage_async(unsigned sbase,
                                            const __nv_bfloat16* __restrict__ A,
                                            int ld, int rbase, int kt, int Ktot, int t) {
    const int row = t >> 1;
    const int seg0 = (t & 1) * 4;
    const __nv_bfloat16* rowp = A + (size_t)(rbase + row) * ld;
#pragma unroll
    for (int i = 0; i < 4; i++) {
        int k0 = kt + (seg0 + i) * 8;
        int sb = (Ktot - k0) * 2;
        sb = sb < 0 ? 0 : (sb > 16 ? 16 : sb);
        cp16(sbase + row*(SMW*4) + (seg0 + i)*16, rowp + (sb > 0 ? k0 : 0), sb);
    }
}

// register stage: fp32 source(s), averaged, packed to bf16 words (full 64-k chunks only)
__device__ __forceinline__ void stage_f32avg(unsigned* S, const float* __restrict__ A,
                                             const float* __restrict__ A2,
                                             int ld, int rbase, int kt, int t) {
    const int tr = t >> 3, wg = t & 7;
#pragma unroll
    for (int p = 0; p < 4; p++) {
        int row = p * 32 + tr;
        size_t off = (size_t)(rbase + row) * ld + kt + wg * 8;
        float4 v0 = *(const float4*)(A + off);
        float4 v1 = *(const float4*)(A + off + 4);
        float4 u0 = *(const float4*)(A2 + off);
        float4 u1 = *(const float4*)(A2 + off + 4);
        uint4 w;
        w.x = pack2(0.5f*(v0.x+u0.x), 0.5f*(v0.y+u0.y));
        w.y = pack2(0.5f*(v0.z+u0.z), 0.5f*(v0.w+u0.w));
        w.z = pack2(0.5f*(v1.x+u1.x), 0.5f*(v1.y+u1.y));
        w.w = pack2(0.5f*(v1.z+u1.z), 0.5f*(v1.w+u1.w));
        *(uint4*)&S[row * SMW + wg * 4] = w;
    }
}

// copy stage for bf16 weights (full 64-k chunks only)
__device__ __forceinline__ void stage_copy(unsigned* S, const __nv_bfloat16* __restrict__ B,
                                           int ld, int rbase, int kt, int t) {
    const int row = t >> 1;
    const int seg0 = (t & 1) * 4;
    const __nv_bfloat16* rowp = B + (size_t)(rbase + row) * ld + kt;
#pragma unroll
    for (int i = 0; i < 4; i++)
        *(uint4*)&S[row * SMW + (seg0 + i) * 4] = *(const uint4*)(rowp + (seg0 + i) * 8);
}

// full async double-buffered mainloop: C = A[rbase:+128] @ B[cbase:+128]^T
__device__ __forceinline__ void mm_async(const __nv_bfloat16* __restrict__ A, int lda,
                                         const __nv_bfloat16* __restrict__ B, int ldb,
                                         int Ktot, int rbase, int cbase,
                                         unsigned* SM, int t, int wm, int wn, int lane,
                                         float c[2][8][4]) {
#pragma unroll
    for (int mt = 0; mt < 2; mt++)
#pragma unroll
        for (int nt = 0; nt < 8; nt++)
#pragma unroll
            for (int j = 0; j < 4; j++) c[mt][nt][j] = 0.f;

    const unsigned sm0 = (unsigned)__cvta_generic_to_shared(SM);
    const unsigned TB = TILEW * 4;
    const int nc = (Ktot + 63) >> 6;
    unsigned aoff[2], boff[4];
    frag_offs(lane, wm, wn, aoff, boff);

    stage_async(sm0, A, lda, rbase, 0, Ktot, t);
    stage_async(sm0 + TB, B, ldb, cbase, 0, Ktot, t);
    cp_commit();

    for (int ch = 0; ch < nc; ch++) {
        unsigned abase = sm0 + (unsigned)(ch & 1) * 2 * TB;
        unsigned bbase = abase + TB;
        if (ch + 1 < nc) {
            unsigned na = sm0 + (unsigned)((ch + 1) & 1) * 2 * TB;
            stage_async(na, A, lda, rbase, (ch + 1) << 6, Ktot, t);
            stage_async(na + TB, B, ldb, cbase, (ch + 1) << 6, Ktot, t);
            cp_commit();
            cp_wait<1>();
        } else {
            cp_wait<0>();
        }
        __syncthreads();
        mma_chunk(abase, bbase, aoff, boff, c);
        __syncthreads();
    }
}

// ---------------- pred: min over P=8 ----------------
__global__ __launch_bounds__(256) void k_pred_mma(const int* __restrict__ c1p,
                                                  const int* __restrict__ c2p,
                                                  const float* __restrict__ bpred) {
    extern __shared__ unsigned dsm[];
    const __nv_bfloat16* preds = blockIdx.y ? PTR_P2B : PTR_P1B;
    const int* cond = blockIdx.y ? c2p : c1p;
    const int xoff = blockIdx.y ? 256 : 128;
    const int t = threadIdx.x, lane = t & 31, warp = t >> 5;
    const int wm = warp >> 1, wn = warp & 1;
    const int rbase = blockIdx.x * 128;
    float c[2][8][4];
    mm_async(preds, 64, g_Wpb, 64, 64, rbase, 0, dsm, t, wm, wn, lane, c);

    const int qc = lane & 3;
#pragma unroll
    for (int mt = 0; mt < 2; mt++)
#pragma unroll
        for (int nt = 0; nt < 8; nt++)
#pragma unroll
            for (int j = 0; j < 4; j++) {
                float v = c[mt][nt][j];
                v = fminf(v, __shfl_xor_sync(0xffffffffu, v, 4));
                v = fminf(v, __shfl_xor_sync(0xffffffffu, v, 8));
                v = fminf(v, __shfl_xor_sync(0xffffffffu, v, 16));
                c[mt][nt][j] = v;
            }
    if (lane < 4) {
#pragma unroll
        for (int mt = 0; mt < 2; mt++) {
            int or0 = (rbase + wm * 32 + mt * 16) >> 3;
#pragma unroll
            for (int nt = 0; nt < 8; nt++)
#pragma unroll
                for (int j = 0; j < 4; j++) {
                    int orow = or0 + ((j >= 2) ? 1 : 0);
                    int col = wn * 64 + nt * 8 + qc * 2 + (j & 1);
                    float val = (c[mt][nt][j] + bpred[col]) * (float)cond[orow];
                    PTR_XB[(size_t)orow * XK + xoff + col] = __float2bfloat16(val);
                }
        }
    }
}

// ---------------- bitmap ----------------
__global__ __launch_bounds__(256) void k_bm_mma(const float* __restrict__ bbm,
                                                const int* __restrict__ hc) {
    extern __shared__ unsigned dsm[];
    const int t = threadIdx.x, lane = t & 31, warp = t >> 5;
    const int wm = warp >> 1, wn = warp & 1;
    const int rbase = blockIdx.x * 128;
    float c[2][8][4];
    mm_async(PTR_BMB, BMV, g_Wbmb, BMV, BMV, rbase, 0, dsm, t, wm, wn, lane, c);

    const int qr = lane >> 2, qc = lane & 3;
#pragma unroll
    for (int mt = 0; mt < 2; mt++)
#pragma unroll
        for (int j = 0; j < 4; j++) {
            int r = rbase + wm * 32 + mt * 16 + qr + ((j >= 2) ? 8 : 0);
            float has = (float)hc[r];
#pragma unroll
            for (int nt = 0; nt < 8; nt++) {
                int col = wn * 64 + nt * 8 + qc * 2 + (j & 1);
                PTR_XB[(size_t)r * XK + 384 + col] = __float2bfloat16((c[mt][nt][j] + bbm[col]) * has);
            }
        }
}

// ---------------- gi ----------------
__global__ __launch_bounds__(256) void k_gi_mma(const float* __restrict__ bih) {
    extern __shared__ unsigned dsm[];
    const int t = threadIdx.x, lane = t & 31, warp = t >> 5;
    const int wm = warp >> 1, wn = warp & 1;
    const int rbase = blockIdx.x * 128;
    const int cbase = blockIdx.y * 128;
    float c[2][8][4];
    mm_async(PTR_XB, XK, g_Wihb, XK, XK, rbase, cbase, dsm, t, wm, wn, lane, c);

    const int qr = lane >> 2, qc = lane & 3;
#pragma unroll
    for (int mt = 0; mt < 2; mt++)
#pragma unroll
        for (int j = 0; j < 4; j++) {
            int r = rbase + wm * 32 + mt * 16 + qr + ((j >= 2) ? 8 : 0);
            int n = r % Nn, b = r / Nn;
            size_t obase = ((size_t)n * Bsz + b) * G3;
#pragma unroll
            for (int nt = 0; nt < 8; nt++) {
                int g = cbase + wn * 64 + nt * 8 + qc * 2 + (j & 1);
                PTR_GI[obase + g] = c[mt][nt][j] + bih[g];
            }
        }
}

// ---------------- gh: per-level gh[node][b][g] = 0.5(Hl+Hr) @ Whh^T ----------------
__global__ __launch_bounds__(256) void k_gh_mma(const int* __restrict__ li,
                                                const int* __restrict__ ri,
                                                int level) {
    extern __shared__ unsigned dsm[];
    const int slot = blockIdx.z;
    if (slot >= g_levcnt[level]) return;
    const int node = g_levels[level*32 + slot];
    const int l = li[node], r = ri[node];
    const int t = threadIdx.x, lane = t & 31, warp = t >> 5;
    const int wm = warp >> 1, wn = warp & 1;
    const int rbase = blockIdx.x * 128;
    const int cbase = blockIdx.y * 128;
    const float* Hl = PTR_H + (size_t)l * Bsz * HID;
    const float* Hr = PTR_H + (size_t)r * Bsz * HID;

    float c[2][8][4];
#pragma unroll
    for (int mt = 0; mt < 2; mt++)
#pragma unroll
        for (int nt = 0; nt < 8; nt++)
#pragma unroll
            for (int j = 0; j < 4; j++) c[mt][nt][j] = 0.f;

    unsigned aoff[2], boff[4];
    frag_offs(lane, wm, wn, aoff, boff);
    const unsigned sm0 = (unsigned)__cvta_generic_to_shared(dsm);
    const unsigned TB = TILEW * 4;

    for (int ch = 0; ch < 2; ch++) {
        stage_f32avg(dsm, Hl, Hr, HID, rbase, ch * 64, t);
        stage_copy(dsm + TILEW, g_Whhb, HID, cbase, ch * 64, t);
        __syncthreads();
        mma_chunk(sm0, sm0 + TB, aoff, boff, c);
        __syncthreads();
    }

    const int qr = lane >> 2, qc = lane & 3;
#pragma unroll
    for (int mt = 0; mt < 2; mt++)
#pragma unroll
        for (int j = 0; j < 4; j++) {
            int b = rbase + wm * 32 + mt * 16 + qr + ((j >= 2) ? 8 : 0);
            size_t obase = ((size_t)node * Bsz + b) * G3;
#pragma unroll
            for (int nt = 0; nt < 8; nt++) {
                int g = cbase + wn * 64 + nt * 8 + qc * 2 + (j & 1);
                PTR_GH[obase + g] = c[mt][nt][j];
            }
        }
}

// ---------------- gate: elementwise GRU cell per level ----------------
__global__ __launch_bounds__(256) void k_gate(const int* __restrict__ li,
                                              const int* __restrict__ ri,
                                              const float* __restrict__ bhh,
                                              int level) {
    const int slot = blockIdx.y;
    if (slot >= g_levcnt[level]) return;
    const int node = g_levels[level*32 + slot];
    const int l = li[node], r = ri[node];
    const int idx = blockIdx.x * 256 + threadIdx.x;
    const int b = idx >> 7, g = idx & 127;
    const size_t gib = ((size_t)node * Bsz + b) * G3;
    const float br = bhh[g], bz = bhh[128+g], bn = bhh[256+g];
    float hv, ghr, ghz, ghn;
    if (l < 0) {
        hv = 0.f; ghr = br; ghz = bz; ghn = bn;
    } else {
        hv = 0.5f * (PTR_H[(size_t)l*Bsz*HID + b*HID + g] + PTR_H[(size_t)r*Bsz*HID + b*HID + g]);
        ghr = PTR_GH[gib + g] + br;
        ghz = PTR_GH[gib + 128 + g] + bz;
        ghn = PTR_GH[gib + 256 + g] + bn;
    }
    float rg = 1.f/(1.f + expf(-(PTR_GI[gib + g] + ghr)));
    float zg = 1.f/(1.f + expf(-(PTR_GI[gib + 128 + g] + ghz)));
    float ng = tanhf(PTR_GI[gib + 256 + g] + rg * ghn);
    PTR_H[((size_t)node * Bsz + b) * HID + g] = (1.f - zg) * ng + zg * hv;
}

// ---------------- opemb (fp32, small) -> bf16 x ----------------
__global__ __launch_bounds__(256) void k_opemb(const float* __restrict__ op,
                                               const float* __restrict__ ex,
                                               const float* __restrict__ bop) {
    __shared__ float As[16][68];
    __shared__ float Bs[16][128];
    const int t = threadIdx.x;
    const int rbase = blockIdx.x * 64;
    const int ty = t >> 5, tx = t & 31;
    const int row0 = ty * 8, col0 = tx * 4;
    float acc[8][4];
#pragma unroll
    for (int i = 0; i < 8; i++)
#pragma unroll
        for (int j = 0; j < 4; j++) acc[i][j] = 0.f;

    for (int kt = 0; kt < 96; kt += 16) {
#pragma unroll
        for (int i = 0; i < 4; i++) {
            int idx = t + i * 256;
            int row = idx >> 4, kk = idx & 15;
            int k = kt + kk;
            As[kk][row] = (k < 32) ? op[(size_t)(rbase+row)*32 + k]
                                   : ex[(size_t)(rbase+row)*64 + (k-32)];
        }
#pragma unroll
        for (int i = 0; i < 8; i++) {
            int idx = t + i * 256;
            int kk = idx >> 7, c = idx & 127;
            Bs[kk][c] = g_WopT[(kt+kk)*128 + c];
        }
        __syncthreads();
#pragma unroll
        for (int kk = 0; kk < 16; kk++) {
            float4 a0 = *(const float4*)&As[kk][row0];
            float4 a1 = *(const float4*)&As[kk][row0+4];
            float4 b  = *(const float4*)&Bs[kk][col0];
            float a[8] = {a0.x,a0.y,a0.z,a0.w,a1.x,a1.y,a1.z,a1.w};
            float bb[4]= {b.x,b.y,b.z,b.w};
#pragma unroll
            for (int i = 0; i < 8; i++)
#pragma unroll
                for (int j = 0; j < 4; j++) acc[i][j] += a[i]*bb[j];
        }
        __syncthreads();
    }
#pragma unroll
    for (int i = 0; i < 8; i++) {
        int r = rbase + row0 + i;
#pragma unroll
        for (int j = 0; j < 4; j++)
            PTR_XB[(size_t)r*XK + col0 + j] = __float2bfloat16(acc[i][j] + bop[col0+j]);
    }
}

// ---------------- heads ----------------
__global__ __launch_bounds__(128) void k_heads(const float* __restrict__ W2a, const float* __restrict__ b2a,
                                               const float* __restrict__ W3a, const float* __restrict__ b3a,
                                               const float* __restrict__ Woa, const float* __restrict__ boa,
                                               const float* __restrict__ W2b, const float* __restrict__ b2b,
                                               const float* __restrict__ W3b, const float* __restrict__ b3b,
                                               const float* __restrict__ Wob, const float* __restrict__ bob,
                                               float* __restrict__ out) {
    const int b = blockIdx.x, head = blockIdx.y, t = threadIdx.x;
    const float* W2 = head ? W2b : W2a;  const float* b2 = head ? b2b : b2a;
    const float* W3 = head ? W3b : W3a;  const float* b3 = head ? b3b : b3a;
    const float* Wo = head ? Wob : Woa;  const float* bo = head ? bob : boa;

    __shared__ float s0[128], s1[128], red[4];
    s0[t] = PTR_H[((size_t)(Nn-1)*Bsz + b)*HID + t];
    __syncthreads();
    float acc = b2[t];
#pragma unroll 8
    for (int k = 0; k < 128; k++) acc += s0[k] * W2[t*128 + k];
    s1[t] = fmaxf(acc, 0.f);
    __syncthreads();
    acc = b3[t];
#pragma unroll 8
    for (int k = 0; k < 128; k++) acc += s1[k] * W3[t*128 + k];
    float h2 = fmaxf(acc, 0.f);
    float v = h2 * Wo[t];
#pragma unroll
    for (int off = 16; off; off >>= 1) v += __shfl_down_sync(0xffffffffu, v, off);
    if ((t & 31) == 0) red[t >> 5] = v;
    __syncthreads();
    if (t == 0) {
        float s = red[0] + red[1] + red[2] + red[3] + bo[0];
        out[head * Bsz + b] = 1.f/(1.f + expf(-s));
    }
}

// ---------------- launcher ----------------
extern "C" void kernel_launch(void* const* d_in, const int* in_sizes, int n_in,
                              void* d_out, int out_size) {
    const float* op    = (const float*)d_in[0];
    const float* ex    = (const float*)d_in[1];
    const float* p1    = (const float*)d_in[2];
    const float* p2    = (const float*)d_in[3];
    const int*   c1p   = (const int*)  d_in[4];
    const int*   c2p   = (const int*)  d_in[5];
    const int*   hc    = (const int*)  d_in[6];
    const float* bmp   = (const float*)d_in[7];
    const int*   li    = (const int*)  d_in[8];
    const int*   ri    = (const int*)  d_in[9];
    const float* Wop   = (const float*)d_in[10];
    const float* bop   = (const float*)d_in[11];
    const float* Wpred = (const float*)d_in[12];
    const float* bpred = (const float*)d_in[13];
    const float* Wbm   = (const float*)d_in[14];
    const float* bbm   = (const float*)d_in[15];
    const float* Wih   = (const float*)d_in[16];
    const float* bih   = (const float*)d_in[17];
    const float* Whh   = (const float*)d_in[18];
    const float* bhh   = (const float*)d_in[19];
    const float* W2t1  = (const float*)d_in[20];
    const float* b2t1  = (const float*)d_in[21];
    const float* W3t1  = (const float*)d_in[22];
    const float* b3t1  = (const float*)d_in[23];
    const float* Wot1  = (const float*)d_in[24];
    const float* bot1  = (const float*)d_in[25];
    const float* W2t2  = (const float*)d_in[26];
    const float* b2t2  = (const float*)d_in[27];
    const float* W3t2  = (const float*)d_in[28];
    const float* b3t2  = (const float*)d_in[29];
    const float* Wot2  = (const float*)d_in[30];
    const float* bot2  = (const float*)d_in[31];
    float* out = (float*)d_out;

    cudaFuncSetAttribute(k_pred_mma, cudaFuncAttributeMaxDynamicSharedMemorySize, DSMEM_BYTES);
    cudaFuncSetAttribute(k_bm_mma,   cudaFuncAttributeMaxDynamicSharedMemorySize, DSMEM_BYTES);
    cudaFuncSetAttribute(k_gi_mma,   cudaFuncAttributeMaxDynamicSharedMemorySize, DSMEM_BYTES);
    cudaFuncSetAttribute(k_gh_mma,   cudaFuncAttributeMaxDynamicSharedMemorySize, GH_SMEM);

    // device symbol addresses for k_cvt destinations
    __nv_bfloat16 *d_p1b, *d_p2b, *d_bmb;
    {
        unsigned char* base;
        cudaGetSymbolAddress((void**)&base, g_pool);
        d_p1b = (__nv_bfloat16*)(base + OFF_P1B);
        d_p2b = (__nv_bfloat16*)(base + OFF_P2B);
        d_bmb = (__nv_bfloat16*)(base + OFF_BMB);
    }

    k_prep<<<1540, 256>>>(Wop, Wpred, Wbm, Wih, Whh);
    k_depth<<<1, 1>>>(li);
    k_cvt<<<2048, 256>>>(p1, d_p1b, NP1);
    k_cvt<<<2048, 256>>>(p2, d_p2b, NP1);
    k_cvt<<<2048, 256>>>(bmp, d_bmb, NBM);
    k_opemb<<<Rr/64, 256>>>(op, ex, bop);
    k_pred_mma<<<dim3((Rr*8)/128, 2), 256, DSMEM_BYTES>>>(c1p, c2p, bpred);
    k_bm_mma<<<Rr/128, 256, DSMEM_BYTES>>>(bbm, hc);
    k_gi_mma<<<dim3(Rr/128, 3), 256, DSMEM_BYTES>>>(bih);
    k_gate<<<dim3(512, 32), 256>>>(li, ri, bhh, 1);
    for (int lvl = 2; lvl <= 6; lvl++) {
        k_gh_mma<<<dim3(8, 3, 16), 256, GH_SMEM>>>(li, ri, lvl);
        k_gate<<<dim3(512, 16), 256>>>(li, ri, bhh, lvl);
    }
    k_heads<<<dim3(Bsz, 2), 128>>>(W2t1, b2t1, W3t1, b3t1, Wot1, bot1,
                                   W2t2, b2t2, W3t2, b3t2, Wot2, bot2, out);
}

// round 7
// speedup vs baseline: 2.2431x; 1.0034x over previous
#include <cuda_runtime.h>
#include <cuda_bf16.h>
#include <math.h>

#define Bsz 1024
#define Nn  63
#define Rr  (Bsz*Nn)      // 64512
#define HID 128
#define G3  384
#define XK  512
#define BMV 1000

#define SMW 36            // words per smem row (32 data words = 64 bf16 + 4 pad)
#define TILEW (128*SMW)   // words per 128-row tile
#define DSMEM_BYTES (4*TILEW*4)   // 2 buffers x (A+B) tiles = 72KB
#define GH_SMEM (2*TILEW*4)       // 1 buffer x (A+B) = 36KB

#define NP1 ((size_t)Rr*8*64)     // 33030144 elems
#define NBM ((size_t)Rr*BMV)      // 64512000 elems
#define NX  ((size_t)Rr*XK)       // 33030144 elems

// ---------------- aliased scratch pool (phase-disjoint lifetimes) ----------------
// region A [0, 132MB):   p1b (66MB) + p2b (66MB)   [cvt -> pred]
//                        then g_gi (99MB, float)    [gi -> gates]
// region B [132, 261MB): bmb (129MB)               [cvt -> bm]
//                        then g_gh (99MB, float)    [recurrence]
// region C [261, 327MB): xb (66MB)                 [opemb/pred/bm -> gi]
// region D [327, 360MB): g_H (33MB, float)         [recurrence -> heads]
#define OFF_P1B ((size_t)0)
#define OFF_P2B ((size_t)66060288)
#define OFF_GI  ((size_t)0)
#define OFF_BMB ((size_t)132120576)
#define OFF_GH  ((size_t)132120576)
#define OFF_XB  ((size_t)261144576)
#define OFF_H   ((size_t)327204864)
#define POOL_BYTES ((size_t)360235008)

__device__ __align__(128) unsigned char g_pool[POOL_BYTES];

#define PTR_P1B ((__nv_bfloat16*)(g_pool + OFF_P1B))
#define PTR_P2B ((__nv_bfloat16*)(g_pool + OFF_P2B))
#define PTR_GI  ((float*)(g_pool + OFF_GI))
#define PTR_BMB ((__nv_bfloat16*)(g_pool + OFF_BMB))
#define PTR_GH  ((float*)(g_pool + OFF_GH))
#define PTR_XB  ((__nv_bfloat16*)(g_pool + OFF_XB))
#define PTR_H   ((float*)(g_pool + OFF_H))

__device__ float g_WopT [96*128];
__device__ __nv_bfloat16 g_Wpb  [128*64];
__device__ __nv_bfloat16 g_Wbmb [128*BMV];
__device__ __nv_bfloat16 g_Wihb [G3*XK];
__device__ __nv_bfloat16 g_Whhb [G3*HID];
__device__ int g_levels[8*32];
__device__ int g_levcnt[8];

// ---------------- prep: transpose Wop (fp32) + convert weights to bf16 ----------------
__global__ void k_prep(const float* __restrict__ Wop, const float* __restrict__ Wpred,
                       const float* __restrict__ Wbm, const float* __restrict__ Wih,
                       const float* __restrict__ Whh) {
    int i = blockIdx.x * blockDim.x + threadIdx.x;
    if (i < 128*96) { int r=i/96, c=i-r*96; g_WopT[c*128+r] = Wop[i]; return; }
    i -= 128*96;
    if (i < 128*64)   { g_Wpb[i]   = __float2bfloat16(Wpred[i]); return; }
    i -= 128*64;
    if (i < 128*BMV)  { g_Wbmb[i]  = __float2bfloat16(Wbm[i]);   return; }
    i -= 128*BMV;
    if (i < G3*XK)    { g_Wihb[i]  = __float2bfloat16(Wih[i]);   return; }
    i -= G3*XK;
    if (i < G3*HID)   { g_Whhb[i]  = __float2bfloat16(Whh[i]);   return; }
}

__global__ void k_depth(const int* __restrict__ li) {
    if (threadIdx.x == 0 && blockIdx.x == 0) {
        int depth[Nn];
        for (int d = 0; d < 8; d++) g_levcnt[d] = 0;
        for (int i = 0; i < Nn; i++) {
            int l = li[i];
            depth[i] = (l < 0) ? 1 : (depth[l] + 1);
            int d = depth[i];
            g_levels[d*32 + g_levcnt[d]] = i;
            g_levcnt[d]++;
        }
    }
}

// ---------------- bulk fp32 -> bf16 convert ----------------
__global__ __launch_bounds__(256) void k_cvt(const float* __restrict__ s,
                                             __nv_bfloat16* __restrict__ d, size_t n) {
    size_t i = ((size_t)blockIdx.x * 256 + threadIdx.x) * 4;
    size_t stride = (size_t)gridDim.x * 256 * 4;
    for (; i < n; i += stride) {
        float4 v = *(const float4*)(s + i);
        __nv_bfloat162 lo = __floats2bfloat162_rn(v.x, v.y);
        __nv_bfloat162 hi = __floats2bfloat162_rn(v.z, v.w);
        *(uint2*)(d + i) = make_uint2(*(unsigned*)&lo, *(unsigned*)&hi);
    }
}

// ================= bf16 MMA machinery =================
__device__ __forceinline__ unsigned pack2(float lo, float hi) {
    __nv_bfloat162 h = __floats2bfloat162_rn(lo, hi);
    return *(unsigned*)&h;
}

__device__ __forceinline__ void mma_bf16(float c[4], unsigned a0, unsigned a1,
                                         unsigned a2, unsigned a3,
                                         unsigned b0, unsigned b1) {
    asm volatile("mma.sync.aligned.m16n8k16.row.col.f32.bf16.bf16.f32 "
                 "{%0,%1,%2,%3}, {%4,%5,%6,%7}, {%8,%9}, {%0,%1,%2,%3};"
                 : "+f"(c[0]), "+f"(c[1]), "+f"(c[2]), "+f"(c[3])
                 : "r"(a0), "r"(a1), "r"(a2), "r"(a3), "r"(b0), "r"(b1));
}

__device__ __forceinline__ void ldsm4(unsigned addr, unsigned &r0, unsigned &r1,
                                      unsigned &r2, unsigned &r3) {
    asm volatile("ldmatrix.sync.aligned.m8n8.x4.shared.b16 {%0,%1,%2,%3}, [%4];"
                 : "=r"(r0), "=r"(r1), "=r"(r2), "=r"(r3) : "r"(addr));
}

__device__ __forceinline__ void cp16(unsigned dst, const void* src, int src_bytes) {
    asm volatile("cp.async.cg.shared.global [%0], [%1], 16, %2;\n"
                 :: "r"(dst), "l"(src), "r"(src_bytes));
}
__device__ __forceinline__ void cp_commit() {
    asm volatile("cp.async.commit_group;\n" ::: "memory");
}
template<int N> __device__ __forceinline__ void cp_wait() {
    asm volatile("cp.async.wait_group %0;\n" :: "n"(N) : "memory");
}

// per-lane ldmatrix byte offsets within a tile
__device__ __forceinline__ void frag_offs(int lane, int wm, int wn,
                                          unsigned aoff[2], unsigned boff[4]) {
    int g = lane >> 3, ri = lane & 7;
#pragma unroll
    for (int mt = 0; mt < 2; mt++) {
        int row = wm*32 + mt*16 + (g & 1)*8 + ri;
        aoff[mt] = row * (SMW*4) + (g >> 1) * 16;
    }
#pragma unroll
    for (int p = 0; p < 4; p++) {
        int row = wn*64 + p*16 + (g >> 1)*8 + ri;
        boff[p] = row * (SMW*4) + (g & 1) * 16;
    }
}

// consume one 64-k chunk: 4 k16 steps
__device__ __forceinline__ void mma_chunk(unsigned abase, unsigned bbase,
                                          const unsigned aoff[2], const unsigned boff[4],
                                          float c[2][8][4]) {
#pragma unroll
    for (int ks = 0; ks < 4; ks++) {
        unsigned a[2][4];
#pragma unroll
        for (int mt = 0; mt < 2; mt++)
            ldsm4(abase + aoff[mt] + ks*32, a[mt][0], a[mt][1], a[mt][2], a[mt][3]);
#pragma unroll
        for (int p = 0; p < 4; p++) {
            unsigned b0, b1, b2, b3;
            ldsm4(bbase + boff[p] + ks*32, b0, b1, b2, b3);
            mma_bf16(c[0][2*p],   a[0][0], a[0][1], a[0][2], a[0][3], b0, b1);
            mma_bf16(c[1][2*p],   a[1][0], a[1][1], a[1][2], a[1][3], b0, b1);
            mma_bf16(c[0][2*p+1], a[0][0], a[0][1], a[0][2], a[0][3], b2, b3);
            mma_bf16(c[1][2*p+1], a[1][0], a[1][1], a[1][2], a[1][3], b2, b3);
        }
    }
}

// async stage: 128 rows x 64 k (bf16 source) into tile at smem byte addr sbase
__device__ __forceinline__ void stage_async(unsigned sbase,
                                            const __nv_bfloat16* __restrict__ A,
                                            int ld, int rbase, int kt, int Ktot, int t) {
    const int row = t >> 1;
    const int seg0 = (t & 1) * 4;
    const __nv_bfloat16* rowp = A + (size_t)(rbase + row) * ld;
#pragma unroll
    for (int i = 0; i < 4; i++) {
        int k0 = kt + (seg0 + i) * 8;
        int sb = (Ktot - k0) * 2;
        sb = sb < 0 ? 0 : (sb > 16 ? 16 : sb);
        cp16(sbase + row*(SMW*4) + (seg0 + i)*16, rowp + (sb > 0 ? k0 : 0), sb);
    }
}

// register stage: fp32 source(s), averaged, packed to bf16 words (full 64-k chunks only)
__device__ __forceinline__ void stage_f32avg(unsigned* S, const float* __restrict__ A,
                                             const float* __restrict__ A2,
                                             int ld, int rbase, int kt, int t) {
    const int tr = t >> 3, wg = t & 7;
#pragma unroll
    for (int p = 0; p < 4; p++) {
        int row = p * 32 + tr;
        size_t off = (size_t)(rbase + row) * ld + kt + wg * 8;
        float4 v0 = *(const float4*)(A + off);
        float4 v1 = *(const float4*)(A + off + 4);
        float4 u0 = *(const float4*)(A2 + off);
        float4 u1 = *(const float4*)(A2 + off + 4);
        uint4 w;
        w.x = pack2(0.5f*(v0.x+u0.x), 0.5f*(v0.y+u0.y));
        w.y = pack2(0.5f*(v0.z+u0.z), 0.5f*(v0.w+u0.w));
        w.z = pack2(0.5f*(v1.x+u1.x), 0.5f*(v1.y+u1.y));
        w.w = pack2(0.5f*(v1.z+u1.z), 0.5f*(v1.w+u1.w));
        *(uint4*)&S[row * SMW + wg * 4] = w;
    }
}

// copy stage for bf16 weights (full 64-k chunks only)
__device__ __forceinline__ void stage_copy(unsigned* S, const __nv_bfloat16* __restrict__ B,
                                           int ld, int rbase, int kt, int t) {
    const int row = t >> 1;
    const int seg0 = (t & 1) * 4;
    const __nv_bfloat16* rowp = B + (size_t)(rbase + row) * ld + kt;
#pragma unroll
    for (int i = 0; i < 4; i++)
        *(uint4*)&S[row * SMW + (seg0 + i) * 4] = *(const uint4*)(rowp + (seg0 + i) * 8);
}

// full async double-buffered mainloop: C = A[rbase:+128] @ B[cbase:+128]^T
__device__ __forceinline__ void mm_async(const __nv_bfloat16* __restrict__ A, int lda,
                                         const __nv_bfloat16* __restrict__ B, int ldb,
                                         int Ktot, int rbase, int cbase,
                                         unsigned* SM, int t, int wm, int wn, int lane,
                                         float c[2][8][4]) {
#pragma unroll
    for (int mt = 0; mt < 2; mt++)
#pragma unroll
        for (int nt = 0; nt < 8; nt++)
#pragma unroll
            for (int j = 0; j < 4; j++) c[mt][nt][j] = 0.f;

    const unsigned sm0 = (unsigned)__cvta_generic_to_shared(SM);
    const unsigned TB = TILEW * 4;
    const int nc = (Ktot + 63) >> 6;
    unsigned aoff[2], boff[4];
    frag_offs(lane, wm, wn, aoff, boff);

    stage_async(sm0, A, lda, rbase, 0, Ktot, t);
    stage_async(sm0 + TB, B, ldb, cbase, 0, Ktot, t);
    cp_commit();

    for (int ch = 0; ch < nc; ch++) {
        unsigned abase = sm0 + (unsigned)(ch & 1) * 2 * TB;
        unsigned bbase = abase + TB;
        if (ch + 1 < nc) {
            unsigned na = sm0 + (unsigned)((ch + 1) & 1) * 2 * TB;
            stage_async(na, A, lda, rbase, (ch + 1) << 6, Ktot, t);
            stage_async(na + TB, B, ldb, cbase, (ch + 1) << 6, Ktot, t);
            cp_commit();
            cp_wait<1>();
        } else {
            cp_wait<0>();
        }
        __syncthreads();
        mma_chunk(abase, bbase, aoff, boff, c);
        __syncthreads();
    }
}

// ---------------- pred: min over P=8 ----------------
__global__ __launch_bounds__(256) void k_pred_mma(const int* __restrict__ c1p,
                                                  const int* __restrict__ c2p,
                                                  const float* __restrict__ bpred) {
    extern __shared__ unsigned dsm[];
    const __nv_bfloat16* preds = blockIdx.y ? PTR_P2B : PTR_P1B;
    const int* cond = blockIdx.y ? c2p : c1p;
    const int xoff = blockIdx.y ? 256 : 128;
    const int t = threadIdx.x, lane = t & 31, warp = t >> 5;
    const int wm = warp >> 1, wn = warp & 1;
    const int rbase = blockIdx.x * 128;
    float c[2][8][4];
    mm_async(preds, 64, g_Wpb, 64, 64, rbase, 0, dsm, t, wm, wn, lane, c);

    const int qc = lane & 3;
#pragma unroll
    for (int mt = 0; mt < 2; mt++)
#pragma unroll
        for (int nt = 0; nt < 8; nt++)
#pragma unroll
            for (int j = 0; j < 4; j++) {
                float v = c[mt][nt][j];
                v = fminf(v, __shfl_xor_sync(0xffffffffu, v, 4));
                v = fminf(v, __shfl_xor_sync(0xffffffffu, v, 8));
                v = fminf(v, __shfl_xor_sync(0xffffffffu, v, 16));
                c[mt][nt][j] = v;
            }
    if (lane < 4) {
#pragma unroll
        for (int mt = 0; mt < 2; mt++) {
            int or0 = (rbase + wm * 32 + mt * 16) >> 3;
#pragma unroll
            for (int nt = 0; nt < 8; nt++)
#pragma unroll
                for (int j = 0; j < 4; j++) {
                    int orow = or0 + ((j >= 2) ? 1 : 0);
                    int col = wn * 64 + nt * 8 + qc * 2 + (j & 1);
                    float val = (c[mt][nt][j] + bpred[col]) * (float)cond[orow];
                    PTR_XB[(size_t)orow * XK + xoff + col] = __float2bfloat16(val);
                }
        }
    }
}

// ---------------- bitmap ----------------
__global__ __launch_bounds__(256) void k_bm_mma(const float* __restrict__ bbm,
                                                const int* __restrict__ hc) {
    extern __shared__ unsigned dsm[];
    const int t = threadIdx.x, lane = t & 31, warp = t >> 5;
    const int wm = warp >> 1, wn = warp & 1;
    const int rbase = blockIdx.x * 128;
    float c[2][8][4];
    mm_async(PTR_BMB, BMV, g_Wbmb, BMV, BMV, rbase, 0, dsm, t, wm, wn, lane, c);

    const int qr = lane >> 2, qc = lane & 3;
#pragma unroll
    for (int mt = 0; mt < 2; mt++)
#pragma unroll
        for (int j = 0; j < 4; j++) {
            int r = rbase + wm * 32 + mt * 16 + qr + ((j >= 2) ? 8 : 0);
            float has = (float)hc[r];
#pragma unroll
            for (int nt = 0; nt < 8; nt++) {
                int col = wn * 64 + nt * 8 + qc * 2 + (j & 1);
                PTR_XB[(size_t)r * XK + 384 + col] = __float2bfloat16((c[mt][nt][j] + bbm[col]) * has);
            }
        }
}

// ---------------- gi ----------------
__global__ __launch_bounds__(256) void k_gi_mma(const float* __restrict__ bih) {
    extern __shared__ unsigned dsm[];
    const int t = threadIdx.x, lane = t & 31, warp = t >> 5;
    const int wm = warp >> 1, wn = warp & 1;
    const int rbase = blockIdx.x * 128;
    const int cbase = blockIdx.y * 128;
    float c[2][8][4];
    mm_async(PTR_XB, XK, g_Wihb, XK, XK, rbase, cbase, dsm, t, wm, wn, lane, c);

    const int qr = lane >> 2, qc = lane & 3;
#pragma unroll
    for (int mt = 0; mt < 2; mt++)
#pragma unroll
        for (int j = 0; j < 4; j++) {
            int r = rbase + wm * 32 + mt * 16 + qr + ((j >= 2) ? 8 : 0);
            int n = r % Nn, b = r / Nn;
            size_t obase = ((size_t)n * Bsz + b) * G3;
#pragma unroll
            for (int nt = 0; nt < 8; nt++) {
                int g = cbase + wn * 64 + nt * 8 + qc * 2 + (j & 1);
                PTR_GI[obase + g] = c[mt][nt][j] + bih[g];
            }
        }
}

// ---------------- gh: per-level gh[node][b][g] = 0.5(Hl+Hr) @ Whh^T ----------------
__global__ __launch_bounds__(256) void k_gh_mma(const int* __restrict__ li,
                                                const int* __restrict__ ri,
                                                int level) {
    extern __shared__ unsigned dsm[];
    const int slot = blockIdx.z;
    if (slot >= g_levcnt[level]) return;
    const int node = g_levels[level*32 + slot];
    const int l = li[node], r = ri[node];
    const int t = threadIdx.x, lane = t & 31, warp = t >> 5;
    const int wm = warp >> 1, wn = warp & 1;
    const int rbase = blockIdx.x * 128;
    const int cbase = blockIdx.y * 128;
    const float* Hl = PTR_H + (size_t)l * Bsz * HID;
    const float* Hr = PTR_H + (size_t)r * Bsz * HID;

    float c[2][8][4];
#pragma unroll
    for (int mt = 0; mt < 2; mt++)
#pragma unroll
        for (int nt = 0; nt < 8; nt++)
#pragma unroll
            for (int j = 0; j < 4; j++) c[mt][nt][j] = 0.f;

    unsigned aoff[2], boff[4];
    frag_offs(lane, wm, wn, aoff, boff);
    const unsigned sm0 = (unsigned)__cvta_generic_to_shared(dsm);
    const unsigned TB = TILEW * 4;

    for (int ch = 0; ch < 2; ch++) {
        stage_f32avg(dsm, Hl, Hr, HID, rbase, ch * 64, t);
        stage_copy(dsm + TILEW, g_Whhb, HID, cbase, ch * 64, t);
        __syncthreads();
        mma_chunk(sm0, sm0 + TB, aoff, boff, c);
        __syncthreads();
    }

    const int qr = lane >> 2, qc = lane & 3;
#pragma unroll
    for (int mt = 0; mt < 2; mt++)
#pragma unroll
        for (int j = 0; j < 4; j++) {
            int b = rbase + wm * 32 + mt * 16 + qr + ((j >= 2) ? 8 : 0);
            size_t obase = ((size_t)node * Bsz + b) * G3;
#pragma unroll
            for (int nt = 0; nt < 8; nt++) {
                int g = cbase + wn * 64 + nt * 8 + qc * 2 + (j & 1);
                PTR_GH[obase + g] = c[mt][nt][j];
            }
        }
}

// ---------------- gate: elementwise GRU cell per level ----------------
__global__ __launch_bounds__(256) void k_gate(const int* __restrict__ li,
                                              const int* __restrict__ ri,
                                              const float* __restrict__ bhh,
                                              int level) {
    const int slot = blockIdx.y;
    if (slot >= g_levcnt[level]) return;
    const int node = g_levels[level*32 + slot];
    const int l = li[node], r = ri[node];
    const int idx = blockIdx.x * 256 + threadIdx.x;
    const int b = idx >> 7, g = idx & 127;
    const size_t gib = ((size_t)node * Bsz + b) * G3;
    const float br = bhh[g], bz = bhh[128+g], bn = bhh[256+g];
    float hv, ghr, ghz, ghn;
    if (l < 0) {
        hv = 0.f; ghr = br; ghz = bz; ghn = bn;
    } else {
        hv = 0.5f * (PTR_H[(size_t)l*Bsz*HID + b*HID + g] + PTR_H[(size_t)r*Bsz*HID + b*HID + g]);
        ghr = PTR_GH[gib + g] + br;
        ghz = PTR_GH[gib + 128 + g] + bz;
        ghn = PTR_GH[gib + 256 + g] + bn;
    }
    float rg = 1.f/(1.f + expf(-(PTR_GI[gib + g] + ghr)));
    float zg = 1.f/(1.f + expf(-(PTR_GI[gib + 128 + g] + ghz)));
    float ng = tanhf(PTR_GI[gib + 256 + g] + rg * ghn);
    PTR_H[((size_t)node * Bsz + b) * HID + g] = (1.f - zg) * ng + zg * hv;
}

// ---------------- opemb (fp32, small) -> bf16 x ----------------
__global__ __launch_bounds__(256) void k_opemb(const float* __restrict__ op,
                                               const float* __restrict__ ex,
                                               const float* __restrict__ bop) {
    __shared__ float As[16][68];
    __shared__ float Bs[16][128];
    const int t = threadIdx.x;
    const int rbase = blockIdx.x * 64;
    const int ty = t >> 5, tx = t & 31;
    const int row0 = ty * 8, col0 = tx * 4;
    float acc[8][4];
#pragma unroll
    for (int i = 0; i < 8; i++)
#pragma unroll
        for (int j = 0; j < 4; j++) acc[i][j] = 0.f;

    for (int kt = 0; kt < 96; kt += 16) {
#pragma unroll
        for (int i = 0; i < 4; i++) {
            int idx = t + i * 256;
            int row = idx >> 4, kk = idx & 15;
            int k = kt + kk;
            As[kk][row] = (k < 32) ? op[(size_t)(rbase+row)*32 + k]
                                   : ex[(size_t)(rbase+row)*64 + (k-32)];
        }
#pragma unroll
        for (int i = 0; i < 8; i++) {
            int idx = t + i * 256;
            int kk = idx >> 7, c = idx & 127;
            Bs[kk][c] = g_WopT[(kt+kk)*128 + c];
        }
        __syncthreads();
#pragma unroll
        for (int kk = 0; kk < 16; kk++) {
            float4 a0 = *(const float4*)&As[kk][row0];
            float4 a1 = *(const float4*)&As[kk][row0+4];
            float4 b  = *(const float4*)&Bs[kk][col0];
            float a[8] = {a0.x,a0.y,a0.z,a0.w,a1.x,a1.y,a1.z,a1.w};
            float bb[4]= {b.x,b.y,b.z,b.w};
#pragma unroll
            for (int i = 0; i < 8; i++)
#pragma unroll
                for (int j = 0; j < 4; j++) acc[i][j] += a[i]*bb[j];
        }
        __syncthreads();
    }
#pragma unroll
    for (int i = 0; i < 8; i++) {
        int r = rbase + row0 + i;
#pragma unroll
        for (int j = 0; j < 4; j++)
            PTR_XB[(size_t)r*XK + col0 + j] = __float2bfloat16(acc[i][j] + bop[col0+j]);
    }
}

// ---------------- heads ----------------
__global__ __launch_bounds__(128) void k_heads(const float* __restrict__ W2a, const float* __restrict__ b2a,
                                               const float* __restrict__ W3a, const float* __restrict__ b3a,
                                               const float* __restrict__ Woa, const float* __restrict__ boa,
                                               const float* __restrict__ W2b, const float* __restrict__ b2b,
                                               const float* __restrict__ W3b, const float* __restrict__ b3b,
                                               const float* __restrict__ Wob, const float* __restrict__ bob,
                                               float* __restrict__ out) {
    const int b = blockIdx.x, head = blockIdx.y, t = threadIdx.x;
    const float* W2 = head ? W2b : W2a;  const float* b2 = head ? b2b : b2a;
    const float* W3 = head ? W3b : W3a;  const float* b3 = head ? b3b : b3a;
    const float* Wo = head ? Wob : Woa;  const float* bo = head ? bob : boa;

    __shared__ float s0[128], s1[128], red[4];
    s0[t] = PTR_H[((size_t)(Nn-1)*Bsz + b)*HID + t];
    __syncthreads();
    float acc = b2[t];
#pragma unroll 8
    for (int k = 0; k < 128; k++) acc += s0[k] * W2[t*128 + k];
    s1[t] = fmaxf(acc, 0.f);
    __syncthreads();
    acc = b3[t];
#pragma unroll 8
    for (int k = 0; k < 128; k++) acc += s1[k] * W3[t*128 + k];
    float h2 = fmaxf(acc, 0.f);
    float v = h2 * Wo[t];
#pragma unroll
    for (int off = 16; off; off >>= 1) v += __shfl_down_sync(0xffffffffu, v, off);
    if ((t & 31) == 0) red[t >> 5] = v;
    __syncthreads();
    if (t == 0) {
        float s = red[0] + red[1] + red[2] + red[3] + bo[0];
        out[head * Bsz + b] = 1.f/(1.f + expf(-s));
    }
}

// ---------------- launcher ----------------
extern "C" void kernel_launch(void* const* d_in, const int* in_sizes, int n_in,
                              void* d_out, int out_size) {
    const float* op    = (const float*)d_in[0];
    const float* ex    = (const float*)d_in[1];
    const float* p1    = (const float*)d_in[2];
    const float* p2    = (const float*)d_in[3];
    const int*   c1p   = (const int*)  d_in[4];
    const int*   c2p   = (const int*)  d_in[5];
    const int*   hc    = (const int*)  d_in[6];
    const float* bmp   = (const float*)d_in[7];
    const int*   li    = (const int*)  d_in[8];
    const int*   ri    = (const int*)  d_in[9];
    const float* Wop   = (const float*)d_in[10];
    const float* bop   = (const float*)d_in[11];
    const float* Wpred = (const float*)d_in[12];
    const float* bpred = (const float*)d_in[13];
    const float* Wbm   = (const float*)d_in[14];
    const float* bbm   = (const float*)d_in[15];
    const float* Wih   = (const float*)d_in[16];
    const float* bih   = (const float*)d_in[17];
    const float* Whh   = (const float*)d_in[18];
    const float* bhh   = (const float*)d_in[19];
    const float* W2t1  = (const float*)d_in[20];
    const float* b2t1  = (const float*)d_in[21];
    const float* W3t1  = (const float*)d_in[22];
    const float* b3t1  = (const float*)d_in[23];
    const float* Wot1  = (const float*)d_in[24];
    const float* bot1  = (const float*)d_in[25];
    const float* W2t2  = (const float*)d_in[26];
    const float* b2t2  = (const float*)d_in[27];
    const float* W3t2  = (const float*)d_in[28];
    const float* b3t2  = (const float*)d_in[29];
    const float* Wot2  = (const float*)d_in[30];
    const float* bot2  = (const float*)d_in[31];
    float* out = (float*)d_out;

    cudaFuncSetAttribute(k_pred_mma, cudaFuncAttributeMaxDynamicSharedMemorySize, DSMEM_BYTES);
    cudaFuncSetAttribute(k_bm_mma,   cudaFuncAttributeMaxDynamicSharedMemorySize, DSMEM_BYTES);
    cudaFuncSetAttribute(k_gi_mma,   cudaFuncAttributeMaxDynamicSharedMemorySize, DSMEM_BYTES);
    cudaFuncSetAttribute(k_gh_mma,   cudaFuncAttributeMaxDynamicSharedMemorySize, GH_SMEM);

    // device symbol addresses for k_cvt destinations
    __nv_bfloat16 *d_p1b, *d_p2b, *d_bmb;
    {
        unsigned char* base;
        cudaGetSymbolAddress((void**)&base, g_pool);
        d_p1b = (__nv_bfloat16*)(base + OFF_P1B);
        d_p2b = (__nv_bfloat16*)(base + OFF_P2B);
        d_bmb = (__nv_bfloat16*)(base + OFF_BMB);
    }

    k_prep<<<1540, 256>>>(Wop, Wpred, Wbm, Wih, Whh);
    k_depth<<<1, 1>>>(li);
    k_cvt<<<2048, 256>>>(p1, d_p1b, NP1);
    k_cvt<<<2048, 256>>>(p2, d_p2b, NP1);
    k_cvt<<<2048, 256>>>(bmp, d_bmb, NBM);
    k_opemb<<<Rr/64, 256>>>(op, ex, bop);
    k_pred_mma<<<dim3((Rr*8)/128, 2), 256, DSMEM_BYTES>>>(c1p, c2p, bpred);
    k_bm_mma<<<Rr/128, 256, DSMEM_BYTES>>>(bbm, hc);
    k_gi_mma<<<dim3(Rr/128, 3), 256, DSMEM_BYTES>>>(bih);
    k_gate<<<dim3(512, 32), 256>>>(li, ri, bhh, 1);
    for (int lvl = 2; lvl <= 6; lvl++) {
        k_gh_mma<<<dim3(8, 3, 16), 256, GH_SMEM>>>(li, ri, lvl);
        k_gate<<<dim3(512, 16), 256>>>(li, ri, bhh, lvl);
    }
    k_heads<<<dim3(Bsz, 2), 128>>>(W2t1, b2t1, W3t1, b3t1, Wot1, bot1,
                                   W2t2, b2t2, W3t2, b3t2, Wot2, bot2, out);
}